// round 1
// baseline (speedup 1.0000x reference)
#include <cuda_runtime.h>

// Problem constants
namespace {
constexpr int Bn = 32;    // batch
constexpr int Tn = 1024;  // time
constexpr int Dn = 512;   // input dim
constexpr int Un = 512;   // units
constexpr int M  = Bn * Tn;

// GEMM tiling
constexpr int BM = 64, BN = 64, BK = 16;
constexpr int AS_STRIDE = 68;   // padded k-major A tile stride

// Scan config
constexpr int G  = 64;             // persistent blocks
constexpr int UC = Un / G;         // 8 output columns per block
constexpr int RS_STRIDE = Dn + 4;  // 516: conflict-free float4 reads of R rows
constexpr int HS_STRIDE = Dn + 8;  // 520: conflict-free float4 reads of H rows
constexpr int SMEM_SCAN_FLOATS = UC * RS_STRIDE + Bn * HS_STRIDE;  // 20768 floats = 83072 B
}

// Per-block progress flags for the grid-wide step barrier.
__device__ volatile int g_flags[G];

__global__ void init_flags_kernel() {
    if (threadIdx.x < G) g_flags[threadIdx.x] = 0;
}

// ---------------------------------------------------------------------------
// Phase 1: O = X @ W   (fp32 tiled SIMT GEMM, 64x64x16 tiles, 4x4 microtile)
// X: [M, Dn] row-major, W: [Dn, Un] row-major, O: [M, Un]
// ---------------------------------------------------------------------------
__global__ __launch_bounds__(256) void gemm_xw_kernel(
    const float* __restrict__ X, const float* __restrict__ W, float* __restrict__ O)
{
    __shared__ float As[BK][AS_STRIDE];  // k-major (transposed) A tile
    __shared__ float Bs[BK][BN];

    const int bm  = blockIdx.y * BM;
    const int bn  = blockIdx.x * BN;
    const int tid = threadIdx.x;
    const int tx  = tid & 15;        // n microtile index (x4)
    const int ty  = tid >> 4;        // m microtile index (x4)
    const int arow = tid >> 2;       // 0..63  (m row of A tile)
    const int akq  = (tid & 3) << 2; // 0,4,8,12 (k quarter)
    const int brow = tid >> 4;       // 0..15  (k row of B tile)
    const int bcol = (tid & 15) << 2;// 0..60

    float acc[4][4] = {};

    for (int k0 = 0; k0 < Dn; k0 += BK) {
        float4 av = *(const float4*)(X + (size_t)(bm + arow) * Dn + k0 + akq);
        float4 bv = *(const float4*)(W + (size_t)(k0 + brow) * Un + bn + bcol);
        As[akq + 0][arow] = av.x;
        As[akq + 1][arow] = av.y;
        As[akq + 2][arow] = av.z;
        As[akq + 3][arow] = av.w;
        *(float4*)(&Bs[brow][bcol]) = bv;
        __syncthreads();
#pragma unroll
        for (int k = 0; k < BK; k++) {
            float4 a = *(const float4*)(&As[k][ty * 4]);
            float4 b = *(const float4*)(&Bs[k][tx * 4]);
            float am[4] = {a.x, a.y, a.z, a.w};
            float bv4[4] = {b.x, b.y, b.z, b.w};
#pragma unroll
            for (int i = 0; i < 4; i++)
#pragma unroll
                for (int j = 0; j < 4; j++)
                    acc[i][j] += am[i] * bv4[j];
        }
        __syncthreads();
    }

#pragma unroll
    for (int i = 0; i < 4; i++) {
        float4 o = make_float4(acc[i][0], acc[i][1], acc[i][2], acc[i][3]);
        *(float4*)(O + (size_t)(bm + ty * 4 + i) * Un + bn + tx * 4) = o;
    }
}

// ---------------------------------------------------------------------------
// Phase 2: persistent scan.  For t = 1..T-1:  O[:,t,:] += O[:,t-1,:] @ R
// 64 blocks, each owns 8 columns of R (kept in smem). Per step:
//   wait flags -> stage H=O[:,t-1,:] into smem -> compute slice -> write ->
//   fence -> publish flag.
// ---------------------------------------------------------------------------
__global__ __launch_bounds__(256) void scan_kernel(
    const float* __restrict__ R, float* __restrict__ O)
{
    extern __shared__ float smem[];
    float* Rs = smem;                   // [UC][RS_STRIDE]  (R column slice, k-major)
    float* Hs = smem + UC * RS_STRIDE;  // [Bn][HS_STRIDE]  (staged H)

    const int g   = blockIdx.x;
    const int tid = threadIdx.x;
    const int u   = tid & (UC - 1);     // 0..7  local column
    const int b   = tid / UC;           // 0..31 batch row
    const int ug  = g * UC + u;         // global column

    // Load this block's R slice once: Rs[u][k] = R[k][g*UC + u]
    for (int i = tid; i < UC * Dn; i += 256) {
        int k  = i / UC;
        int uu = i - k * UC;
        Rs[uu * RS_STRIDE + k] = R[(size_t)k * Un + g * UC + uu];
    }
    __syncthreads();

    const float* Rrow = Rs + u * RS_STRIDE;

    for (int t = 1; t < Tn; t++) {
        if (t >= 2) {
            // Wait until every block has published step t-1.
            if (tid < G) {
                while (g_flags[tid] < t - 1) { }
            }
            __syncthreads();
            __threadfence();
        }

        // Stage H = O[:, t-1, :] into smem (coalesced, L1-bypassing loads).
        {
            constexpr int NF4 = Bn * (Dn / 4);  // 4096 float4s
            for (int i = tid; i < NF4; i += 256) {
                int bb = i >> 7;       // /128
                int k4 = i & 127;
                float4 v = __ldcg((const float4*)(O + ((size_t)bb * Tn + (t - 1)) * Un) + k4);
                *(float4*)(Hs + bb * HS_STRIDE + k4 * 4) = v;
            }
        }
        __syncthreads();

        const float xw = __ldcg(O + ((size_t)b * Tn + t) * Un + ug);
        const float* hrow = Hs + b * HS_STRIDE;

        float accv[4] = {0.f, 0.f, 0.f, 0.f};
#pragma unroll 8
        for (int k4 = 0; k4 < Dn / 4; k4++) {
            float4 hv = *(const float4*)(hrow + k4 * 4);
            float4 rv = *(const float4*)(Rrow + k4 * 4);
            float p = hv.x * rv.x + hv.y * rv.y + hv.z * rv.z + hv.w * rv.w;
            accv[k4 & 3] += p;
        }
        float hsum = (accv[0] + accv[1]) + (accv[2] + accv[3]);

        O[((size_t)b * Tn + t) * Un + ug] = xw + hsum;

        __threadfence();      // make our slice of O[:,t,:] globally visible
        __syncthreads();      // all threads of this block done writing
        if (tid == 0) g_flags[g] = t;   // publish step t
    }
}

// ---------------------------------------------------------------------------
// Launch: GEMM fills O with XW, flags reset, then the persistent scan.
// All plain stream launches -> graph-capturable, no allocations.
// ---------------------------------------------------------------------------
extern "C" void kernel_launch(void* const* d_in, const int* in_sizes, int n_in,
                              void* d_out, int out_size)
{
    const float* x = (const float*)d_in[0];  // [B, T, D]
    const float* w = (const float*)d_in[1];  // [D, U]
    const float* r = (const float*)d_in[2];  // [U, U]
    float* o = (float*)d_out;                // [B, T, U]

    (void)in_sizes; (void)n_in; (void)out_size;

    dim3 ggrid(Un / BN, M / BM);  // (8, 512)
    gemm_xw_kernel<<<ggrid, 256>>>(x, w, o);

    init_flags_kernel<<<1, 64>>>();

    constexpr size_t scan_smem = SMEM_SCAN_FLOATS * sizeof(float);  // 83072 B
    cudaFuncSetAttribute(scan_kernel, cudaFuncAttributeMaxDynamicSharedMemorySize,
                         (int)scan_smem);
    scan_kernel<<<G, 256, scan_smem>>>(r, o);
}

// round 2
// speedup vs baseline: 3.2884x; 3.2884x over previous
#include <cuda_runtime.h>

namespace {
constexpr int Bn = 32;    // batch
constexpr int Tn = 1024;  // time
constexpr int Dn = 512;   // input dim
constexpr int Un = 512;   // units
constexpr int M  = Bn * Tn;

constexpr int Lc = 32;    // chunk length
constexpr int Cc = Tn / Lc;  // 32 chunks

// GEMM tiling (proven 40 TF/s config from round 1)
constexpr int BM = 64, BN = 64, BK = 16;
constexpr int AS_STRIDE = 68;   // padded k-major A tile stride
}

// ---------------------------------------------------------------------------
// Device scratch (static allocation only — no cudaMalloc allowed)
// ---------------------------------------------------------------------------
__device__ float g_bufA[Un * Un];            // R-power ping
__device__ float g_bufB[Un * Un];            // R-power pong
__device__ float g_carry[Cc * Bn * Un];      // carry_c, layout [c][b][u]
__device__ float g_P0[Cc * Bn * Un];         // correction ping
__device__ float g_P1[Cc * Bn * Un];         // correction pong

// ---------------------------------------------------------------------------
// Generic C = A @ B, A:[M x 512], B:[512 x 512], C:[M x 512]
// grid = (512/BN, M/BM), block = 256.   64x64x16 tiles, 4x4 microtile.
// ---------------------------------------------------------------------------
__global__ __launch_bounds__(256) void gemm_nn_kernel(
    const float* __restrict__ A, const float* __restrict__ B, float* __restrict__ C)
{
    __shared__ float As[BK][AS_STRIDE];
    __shared__ float Bs[BK][BN];

    const int bm  = blockIdx.y * BM;
    const int bn  = blockIdx.x * BN;
    const int tid = threadIdx.x;
    const int tx  = tid & 15;
    const int ty  = tid >> 4;
    const int arow = tid >> 2;
    const int akq  = (tid & 3) << 2;
    const int brow = tid >> 4;
    const int bcol = (tid & 15) << 2;

    float acc[4][4] = {};
    const float* abase = A + (size_t)(bm + arow) * Dn;

    for (int k0 = 0; k0 < Dn; k0 += BK) {
        float4 av = *(const float4*)(abase + k0 + akq);
        float4 bv = *(const float4*)(B + (size_t)(k0 + brow) * Un + bn + bcol);
        As[akq + 0][arow] = av.x;
        As[akq + 1][arow] = av.y;
        As[akq + 2][arow] = av.z;
        As[akq + 3][arow] = av.w;
        *(float4*)(&Bs[brow][bcol]) = bv;
        __syncthreads();
#pragma unroll
        for (int k = 0; k < BK; k++) {
            float4 a = *(const float4*)(&As[k][ty * 4]);
            float4 b = *(const float4*)(&Bs[k][tx * 4]);
            float am[4] = {a.x, a.y, a.z, a.w};
            float bm4[4] = {b.x, b.y, b.z, b.w};
#pragma unroll
            for (int i = 0; i < 4; i++)
#pragma unroll
                for (int j = 0; j < 4; j++)
                    acc[i][j] += am[i] * bm4[j];
        }
        __syncthreads();
    }

#pragma unroll
    for (int i = 0; i < 4; i++) {
        float4 o = make_float4(acc[i][0], acc[i][1], acc[i][2], acc[i][3]);
        *(float4*)(C + (size_t)(bm + ty * 4 + i) * Un + bn + tx * 4) = o;
    }
}

// ---------------------------------------------------------------------------
// Pass 1 local-scan step t (t in 1..Lc-1):
//   for all chunks c, batch b:  O[b, c*Lc + t, :] += O[b, c*Lc + t - 1, :] @ R
// Rows r = c*32 + b  (1024 rows).  grid = (8, 16), block = 256.
// ---------------------------------------------------------------------------
__global__ __launch_bounds__(256) void pass1_step_kernel(
    const float* __restrict__ Rm, float* __restrict__ O, int t)
{
    __shared__ float As[BK][AS_STRIDE];
    __shared__ float Bs[BK][BN];

    const int bm  = blockIdx.y * BM;
    const int bn  = blockIdx.x * BN;
    const int tid = threadIdx.x;
    const int tx  = tid & 15;
    const int ty  = tid >> 4;
    const int arow = tid >> 2;
    const int akq  = (tid & 3) << 2;
    const int brow = tid >> 4;
    const int bcol = (tid & 15) << 2;

    // map A row -> O[b, c*Lc + t - 1, :]
    {
        // nothing
    }
    const int ar = bm + arow;
    const int ac = ar >> 5;
    const int ab = ar & 31;
    const float* abase = O + ((size_t)ab * Tn + (size_t)ac * Lc + (t - 1)) * Un;

    float acc[4][4] = {};

    for (int k0 = 0; k0 < Dn; k0 += BK) {
        float4 av = *(const float4*)(abase + k0 + akq);
        float4 bv = *(const float4*)(Rm + (size_t)(k0 + brow) * Un + bn + bcol);
        As[akq + 0][arow] = av.x;
        As[akq + 1][arow] = av.y;
        As[akq + 2][arow] = av.z;
        As[akq + 3][arow] = av.w;
        *(float4*)(&Bs[brow][bcol]) = bv;
        __syncthreads();
#pragma unroll
        for (int k = 0; k < BK; k++) {
            float4 a = *(const float4*)(&As[k][ty * 4]);
            float4 b = *(const float4*)(&Bs[k][tx * 4]);
            float am[4] = {a.x, a.y, a.z, a.w};
            float bm4[4] = {b.x, b.y, b.z, b.w};
#pragma unroll
            for (int i = 0; i < 4; i++)
#pragma unroll
                for (int j = 0; j < 4; j++)
                    acc[i][j] += am[i] * bm4[j];
        }
        __syncthreads();
    }

#pragma unroll
    for (int i = 0; i < 4; i++) {
        const int row = bm + ty * 4 + i;
        const int c = row >> 5;
        const int b = row & 31;
        float* optr = O + ((size_t)b * Tn + (size_t)c * Lc + t) * Un + bn + tx * 4;
        float4 e = *(const float4*)optr;
        e.x += acc[i][0]; e.y += acc[i][1]; e.z += acc[i][2]; e.w += acc[i][3];
        *(float4*)optr = e;
    }
}

// ---------------------------------------------------------------------------
// Pass 3 correction step t (t in 0..Lc-1):
//   Pout[r,:] = Pin[r,:] @ R      (r = c*32+b, 1024 rows; Pin(t=0)=carry)
//   O[b, c*Lc + t, :] += Pout[r,:]
// ---------------------------------------------------------------------------
__global__ __launch_bounds__(256) void pass3_step_kernel(
    const float* __restrict__ Rm, float* __restrict__ O,
    const float* __restrict__ Pin, float* __restrict__ Pout, int t)
{
    __shared__ float As[BK][AS_STRIDE];
    __shared__ float Bs[BK][BN];

    const int bm  = blockIdx.y * BM;
    const int bn  = blockIdx.x * BN;
    const int tid = threadIdx.x;
    const int tx  = tid & 15;
    const int ty  = tid >> 4;
    const int arow = tid >> 2;
    const int akq  = (tid & 3) << 2;
    const int brow = tid >> 4;
    const int bcol = (tid & 15) << 2;

    const float* abase = Pin + (size_t)(bm + arow) * Un;

    float acc[4][4] = {};

    for (int k0 = 0; k0 < Dn; k0 += BK) {
        float4 av = *(const float4*)(abase + k0 + akq);
        float4 bv = *(const float4*)(Rm + (size_t)(k0 + brow) * Un + bn + bcol);
        As[akq + 0][arow] = av.x;
        As[akq + 1][arow] = av.y;
        As[akq + 2][arow] = av.z;
        As[akq + 3][arow] = av.w;
        *(float4*)(&Bs[brow][bcol]) = bv;
        __syncthreads();
#pragma unroll
        for (int k = 0; k < BK; k++) {
            float4 a = *(const float4*)(&As[k][ty * 4]);
            float4 b = *(const float4*)(&Bs[k][tx * 4]);
            float am[4] = {a.x, a.y, a.z, a.w};
            float bm4[4] = {b.x, b.y, b.z, b.w};
#pragma unroll
            for (int i = 0; i < 4; i++)
#pragma unroll
                for (int j = 0; j < 4; j++)
                    acc[i][j] += am[i] * bm4[j];
        }
        __syncthreads();
    }

#pragma unroll
    for (int i = 0; i < 4; i++) {
        const int row = bm + ty * 4 + i;
        const int c = row >> 5;
        const int b = row & 31;
        float4 p = make_float4(acc[i][0], acc[i][1], acc[i][2], acc[i][3]);
        *(float4*)(Pout + (size_t)row * Un + bn + tx * 4) = p;
        float* optr = O + ((size_t)b * Tn + (size_t)c * Lc + t) * Un + bn + tx * 4;
        float4 e = *(const float4*)optr;
        e.x += p.x; e.y += p.y; e.z += p.z; e.w += p.w;
        *(float4*)optr = e;
    }
}

// ---------------------------------------------------------------------------
// Boundary step c (c in 1..Cc-1):
//   carry[c][b,:] = O[b, c*Lc - 1, :] + carry[c-1][b,:] @ R^Lc
// 32 rows x 512 cols.  grid = 8 (col tiles of 64), block = 256, 2x4 microtile.
// ---------------------------------------------------------------------------
__global__ __launch_bounds__(256) void boundary_step_kernel(
    const float* __restrict__ RL, const float* __restrict__ O,
    float* __restrict__ carry, int c)
{
    __shared__ float As[BK][34];   // 32 rows, padded
    __shared__ float Bs[BK][BN];

    const int bn  = blockIdx.x * BN;
    const int tid = threadIdx.x;
    const int tx  = tid & 15;
    const int ty  = tid >> 4;
    const int brow = tid >> 4;
    const int bcol = (tid & 15) << 2;

    const float* abase = carry + ((size_t)(c - 1) * Bn) * Un;

    float acc[2][4] = {};

    for (int k0 = 0; k0 < Dn; k0 += BK) {
        if (tid < 128) {
            const int arow = tid >> 2;        // 0..31
            const int akq  = (tid & 3) << 2;  // 0,4,8,12
            float4 av = *(const float4*)(abase + (size_t)arow * Un + k0 + akq);
            As[akq + 0][arow] = av.x;
            As[akq + 1][arow] = av.y;
            As[akq + 2][arow] = av.z;
            As[akq + 3][arow] = av.w;
        }
        float4 bv = *(const float4*)(RL + (size_t)(k0 + brow) * Un + bn + bcol);
        *(float4*)(&Bs[brow][bcol]) = bv;
        __syncthreads();
#pragma unroll
        for (int k = 0; k < BK; k++) {
            float2 a = *(const float2*)(&As[k][ty * 2]);
            float4 b = *(const float4*)(&Bs[k][tx * 4]);
            float am[2] = {a.x, a.y};
            float bm4[4] = {b.x, b.y, b.z, b.w};
#pragma unroll
            for (int i = 0; i < 2; i++)
#pragma unroll
                for (int j = 0; j < 4; j++)
                    acc[i][j] += am[i] * bm4[j];
        }
        __syncthreads();
    }

#pragma unroll
    for (int i = 0; i < 2; i++) {
        const int b = ty * 2 + i;   // batch row 0..31
        // l_{c-1, Lc-1} = O[b, c*Lc - 1, :]
        const float* lptr = O + ((size_t)b * Tn + (size_t)c * Lc - 1) * Un + bn + tx * 4;
        float4 l = *(const float4*)lptr;
        float4 o = make_float4(l.x + acc[i][0], l.y + acc[i][1],
                               l.z + acc[i][2], l.w + acc[i][3]);
        *(float4*)(carry + ((size_t)c * Bn + b) * Un + bn + tx * 4) = o;
    }
}

__global__ void zero_carry0_kernel() {
    // zero carry[0] (32 x 512 floats) with 256 threads
    for (int i = threadIdx.x; i < Bn * Un; i += 256) g_carry[i] = 0.0f;
}

// ---------------------------------------------------------------------------
// Launch sequence (all stream-ordered; graph-capturable; no allocations)
// ---------------------------------------------------------------------------
extern "C" void kernel_launch(void* const* d_in, const int* in_sizes, int n_in,
                              void* d_out, int out_size)
{
    const float* x = (const float*)d_in[0];  // [B, T, D] == [M, D] row-major
    const float* w = (const float*)d_in[1];  // [D, U]
    const float* r = (const float*)d_in[2];  // [U, U]
    float* o = (float*)d_out;                // [B, T, U]

    (void)in_sizes; (void)n_in; (void)out_size;

    float *bufA, *bufB, *carry, *p0, *p1;
    cudaGetSymbolAddress((void**)&bufA,  g_bufA);
    cudaGetSymbolAddress((void**)&bufB,  g_bufB);
    cudaGetSymbolAddress((void**)&carry, g_carry);
    cudaGetSymbolAddress((void**)&p0,    g_P0);
    cudaGetSymbolAddress((void**)&p1,    g_P1);

    // Phase 0: O = X @ W
    gemm_nn_kernel<<<dim3(Un / BN, M / BM), 256>>>(x, w, o);

    // R^32 via 5 squarings: A=R^2, B=R^4, A=R^8, B=R^16, A=R^32
    dim3 sq(Un / BN, Un / BM);
    gemm_nn_kernel<<<sq, 256>>>(r, r, bufA);
    gemm_nn_kernel<<<sq, 256>>>(bufA, bufA, bufB);
    gemm_nn_kernel<<<sq, 256>>>(bufB, bufB, bufA);
    gemm_nn_kernel<<<sq, 256>>>(bufA, bufA, bufB);
    gemm_nn_kernel<<<sq, 256>>>(bufB, bufB, bufA);   // bufA = R^Lc

    zero_carry0_kernel<<<1, 256>>>();

    // Pass 1: local scans, 31 sequential big steps
    dim3 pgrid(Un / BN, (Cc * Bn) / BM);   // (8, 16)
    for (int t = 1; t < Lc; t++)
        pass1_step_kernel<<<pgrid, 256>>>(r, o, t);

    // Boundary: 31 sequential small steps
    for (int c = 1; c < Cc; c++)
        boundary_step_kernel<<<Un / BN, 256>>>(bufA, o, carry, c);

    // Pass 3: corrections, 32 sequential big steps (ping-pong P)
    for (int t = 0; t < Lc; t++) {
        const float* pin = (t == 0) ? carry : ((t & 1) ? p0 : p1);
        float* pout = (t & 1) ? p1 : p0;
        pass3_step_kernel<<<pgrid, 256>>>(r, o, pin, pout, t);
    }
}

// round 4
// speedup vs baseline: 4.0750x; 1.2392x over previous
#include <cuda_runtime.h>

namespace {
constexpr int Bn = 32;      // batch
constexpr int Tn = 1024;    // time
constexpr int Dn = 512;     // dims (D == U)
constexpr int M  = Bn * Tn; // 32768

constexpr int Lc = 16;          // chunk length
constexpr int Cc = Tn / Lc;     // 64 chunks
constexpr int Gg = 8;           // carry-scan groups
constexpr int Jg = Cc / Gg;     // 8 chunks per group

constexpr int SZ    = 512 * 512;   // one 512x512 matrix (floats)
constexpr int ROWSZ = 32 * 512;    // one 32x512 block (floats)
constexpr size_t OROW = (size_t)Tn * Dn;  // O row-b stride in floats (524288)

constexpr int BK = 16;
}

// ---------------------------------------------------------------------------
// Static device scratch (no allocations allowed)
// ---------------------------------------------------------------------------
__device__ float g_Rpow[16 * SZ];   // R^1..R^16   (R^t at g_Rpow + (t-1)*SZ)
__device__ float g_Qpow[8 * SZ];    // S^1..S^8, S = R^16
__device__ float g_U[Cc * ROWSZ];   // within-group partial carries u[g][j]
__device__ float g_G[Gg * ROWSZ];   // group carries
__device__ float g_carry[Cc * ROWSZ];

// ---------------------------------------------------------------------------
// 64x64 tile core: acc += A(64x512, row stride 512) @ B(512x512)[:, bn:bn+64]
// block = 256 threads, 4x4 microtile.
// ---------------------------------------------------------------------------
__device__ __forceinline__ void core64(const float* __restrict__ A,
                                       const float* __restrict__ Bm,
                                       int bn, float acc[4][4])
{
    __shared__ float As[BK][68];
    __shared__ float Bs[BK][64];
    const int tid  = threadIdx.x;
    const int tx   = tid & 15;
    const int ty   = tid >> 4;
    const int arow = tid >> 2;
    const int akq  = (tid & 3) << 2;
    const int brow = tid >> 4;
    const int bcol = (tid & 15) << 2;

    for (int k0 = 0; k0 < 512; k0 += BK) {
        float4 av = *(const float4*)(A + (size_t)arow * 512 + k0 + akq);
        float4 bv = *(const float4*)(Bm + (size_t)(k0 + brow) * 512 + bn + bcol);
        As[akq + 0][arow] = av.x;
        As[akq + 1][arow] = av.y;
        As[akq + 2][arow] = av.z;
        As[akq + 3][arow] = av.w;
        *(float4*)(&Bs[brow][bcol]) = bv;
        __syncthreads();
#pragma unroll
        for (int k = 0; k < BK; k++) {
            float4 a = *(const float4*)(&As[k][ty * 4]);
            float4 b = *(const float4*)(&Bs[k][tx * 4]);
            float am[4] = {a.x, a.y, a.z, a.w};
            float bm4[4] = {b.x, b.y, b.z, b.w};
#pragma unroll
            for (int i = 0; i < 4; i++)
#pragma unroll
                for (int j = 0; j < 4; j++)
                    acc[i][j] += am[i] * bm4[j];
        }
        __syncthreads();
    }
}

// C = A @ B   (A: [gridDim.y*64 x 512] contiguous, B: 512x512, C same shape as A-rows x 512)
__global__ __launch_bounds__(256) void gemm_nn_kernel(
    const float* __restrict__ A, const float* __restrict__ B, float* __restrict__ C)
{
    const int bm = blockIdx.y * 64;
    const int bn = blockIdx.x * 64;
    float acc[4][4] = {};
    core64(A + (size_t)bm * 512, B, bn, acc);
    const int tx = threadIdx.x & 15, ty = threadIdx.x >> 4;
#pragma unroll
    for (int i = 0; i < 4; i++) {
        float4 o = make_float4(acc[i][0], acc[i][1], acc[i][2], acc[i][3]);
        *(float4*)(C + (size_t)(bm + ty * 4 + i) * 512 + bn + tx * 4) = o;
    }
}

// Batched power doubling: P[n+1+z] = P[1+z] @ P[n], z = 0..n-1  (1-indexed powers)
__global__ __launch_bounds__(256) void power_level_kernel(float* __restrict__ P, int n)
{
    const int z  = blockIdx.z;
    const int bm = blockIdx.y * 64;
    const int bn = blockIdx.x * 64;
    const float* A = P + (size_t)z * SZ + (size_t)bm * 512;
    const float* B = P + (size_t)(n - 1) * SZ;
    float* C = P + (size_t)(n + z) * SZ;
    float acc[4][4] = {};
    core64(A, B, bn, acc);
    const int tx = threadIdx.x & 15, ty = threadIdx.x >> 4;
#pragma unroll
    for (int i = 0; i < 4; i++) {
        float4 o = make_float4(acc[i][0], acc[i][1], acc[i][2], acc[i][3]);
        *(float4*)(C + (size_t)(bm + ty * 4 + i) * 512 + bn + tx * 4) = o;
    }
}

// ---------------------------------------------------------------------------
// Pass 1 local-scan step t (1..Lc-1):
//   for all c,b:  O[b, c*Lc + t, :] += O[b, c*Lc + t - 1, :] @ R
// rows r = c*32 + b  (2048 rows). grid = (8, 32).
// ---------------------------------------------------------------------------
__global__ __launch_bounds__(256) void pass1_step_kernel(
    const float* __restrict__ Rm, float* __restrict__ O, int t)
{
    __shared__ float As[BK][68];
    __shared__ float Bs[BK][64];
    const int bm  = blockIdx.y * 64;
    const int bn  = blockIdx.x * 64;
    const int tid = threadIdx.x;
    const int tx  = tid & 15;
    const int ty  = tid >> 4;
    const int arow = tid >> 2;
    const int akq  = (tid & 3) << 2;
    const int brow = tid >> 4;
    const int bcol = (tid & 15) << 2;

    const int ar = bm + arow;
    const int ac = ar >> 5;        // chunk
    const int ab = ar & 31;        // batch
    const float* abase = O + ((size_t)ab * Tn + (size_t)ac * Lc + (t - 1)) * 512;

    float acc[4][4] = {};
    for (int k0 = 0; k0 < 512; k0 += BK) {
        float4 av = *(const float4*)(abase + k0 + akq);
        float4 bv = *(const float4*)(Rm + (size_t)(k0 + brow) * 512 + bn + bcol);
        As[akq + 0][arow] = av.x;
        As[akq + 1][arow] = av.y;
        As[akq + 2][arow] = av.z;
        As[akq + 3][arow] = av.w;
        *(float4*)(&Bs[brow][bcol]) = bv;
        __syncthreads();
#pragma unroll
        for (int k = 0; k < BK; k++) {
            float4 a = *(const float4*)(&As[k][ty * 4]);
            float4 b = *(const float4*)(&Bs[k][tx * 4]);
            float am[4] = {a.x, a.y, a.z, a.w};
            float bm4[4] = {b.x, b.y, b.z, b.w};
#pragma unroll
            for (int i = 0; i < 4; i++)
#pragma unroll
                for (int j = 0; j < 4; j++)
                    acc[i][j] += am[i] * bm4[j];
        }
        __syncthreads();
    }

#pragma unroll
    for (int i = 0; i < 4; i++) {
        const int row = bm + ty * 4 + i;
        const int c = row >> 5;
        const int b = row & 31;
        float* optr = O + ((size_t)b * Tn + (size_t)c * Lc + t) * 512 + bn + tx * 4;
        float4 e = *(const float4*)optr;
        e.x += acc[i][0]; e.y += acc[i][1]; e.z += acc[i][2]; e.w += acc[i][3];
        *(float4*)optr = e;
    }
}

// ---------------------------------------------------------------------------
// 32-row tile core + epilogue:  Out = Add + A(32x512) @ B[:, bn:bn+64]
// block = 256 threads, 2x4 microtile.
// ---------------------------------------------------------------------------
__device__ __forceinline__ void core32(const float* __restrict__ A,
                                       const float* __restrict__ Bm,
                                       int bn, float acc[2][4])
{
    __shared__ float As[BK][34];
    __shared__ float Bs[BK][64];
    const int tid = threadIdx.x;
    const int tx  = tid & 15;
    const int ty  = tid >> 4;
    const int brow = tid >> 4;
    const int bcol = (tid & 15) << 2;

    for (int k0 = 0; k0 < 512; k0 += BK) {
        if (tid < 128) {
            const int arow = tid >> 2;
            const int akq  = (tid & 3) << 2;
            float4 av = *(const float4*)(A + (size_t)arow * 512 + k0 + akq);
            As[akq + 0][arow] = av.x;
            As[akq + 1][arow] = av.y;
            As[akq + 2][arow] = av.z;
            As[akq + 3][arow] = av.w;
        }
        float4 bv = *(const float4*)(Bm + (size_t)(k0 + brow) * 512 + bn + bcol);
        *(float4*)(&Bs[brow][bcol]) = bv;
        __syncthreads();
#pragma unroll
        for (int k = 0; k < BK; k++) {
            float2 a = *(const float2*)(&As[k][ty * 2]);
            float4 b = *(const float4*)(&Bs[k][tx * 4]);
            float am[2] = {a.x, a.y};
            float bm4[4] = {b.x, b.y, b.z, b.w};
#pragma unroll
            for (int i = 0; i < 2; i++)
#pragma unroll
                for (int j = 0; j < 4; j++)
                    acc[i][j] += am[i] * bm4[j];
        }
        __syncthreads();
    }
}

__device__ __forceinline__ void epi32(const float acc[2][4], int bn,
                                      const float* __restrict__ addB, size_t addS,
                                      float* __restrict__ outB, size_t outS)
{
    const int tx = threadIdx.x & 15, ty = threadIdx.x >> 4;
#pragma unroll
    for (int i = 0; i < 2; i++) {
        const int b = ty * 2 + i;
        float4 a = *(const float4*)(addB + (size_t)b * addS + bn + tx * 4);
        float4 o = make_float4(a.x + acc[i][0], a.y + acc[i][1],
                               a.z + acc[i][2], a.w + acc[i][3]);
        *(float4*)(outB + (size_t)b * outS + bn + tx * 4) = o;
    }
}

// u_{g,j} = last_{Jg*g+j} + u_{g,j-1} @ S      (grid (8, Gg), j = 1..Jg-1)
__global__ __launch_bounds__(256) void u_step_kernel(
    float* __restrict__ U, const float* __restrict__ Rpow,
    const float* __restrict__ O, int j)
{
    const int g  = blockIdx.y;
    const int bn = blockIdx.x * 64;
    const float* A = U + (size_t)(g * Jg + j - 1) * ROWSZ;
    const float* S = Rpow + (size_t)(Lc - 1) * SZ;     // R^16
    float acc[2][4] = {};
    core32(A, S, bn, acc);
    const int time = Lc * (Jg * g + j) + (Lc - 1);
    epi32(acc, bn, O + (size_t)time * 512, OROW,
          U + (size_t)(g * Jg + j) * ROWSZ, 512);
}

// G_g = U[g][Jg-1] + G_{g-1} @ S^Jg           (grid (8), g = 1..Gg-1)
__global__ __launch_bounds__(256) void g_step_kernel(
    float* __restrict__ G, const float* __restrict__ Qpow,
    const float* __restrict__ U, int g)
{
    const int bn = blockIdx.x * 64;
    const float* A = G + (size_t)(g - 1) * ROWSZ;
    const float* Q8 = Qpow + (size_t)(Jg - 1) * SZ;
    float acc[2][4] = {};
    core32(A, Q8, bn, acc);
    epi32(acc, bn, U + (size_t)(g * Jg + Jg - 1) * ROWSZ, 512,
          G + (size_t)g * ROWSZ, 512);
}

// carry_{Jg*g+j} = U[g][j] + G_{g-1} @ S^{j+1}   (grid (8, 56): g = 1..7, j = 0..7)
__global__ __launch_bounds__(256) void carry_batch_kernel(
    float* __restrict__ carry, const float* __restrict__ G,
    const float* __restrict__ Qpow, const float* __restrict__ U)
{
    const int y  = blockIdx.y;
    const int g  = 1 + (y >> 3);
    const int j  = y & 7;
    const int bn = blockIdx.x * 64;
    const float* A = G + (size_t)(g - 1) * ROWSZ;
    const float* Q = Qpow + (size_t)j * SZ;            // S^{j+1}
    float acc[2][4] = {};
    core32(A, Q, bn, acc);
    epi32(acc, bn, U + (size_t)(g * Jg + j) * ROWSZ, 512,
          carry + (size_t)(g * Jg + j) * ROWSZ, 512);
}

// Pass 3 batched: O[b, Lc*c + t, :] += carry_{c-1} @ R^{t+1}
// grid (8, (Cc-1)*Lc = 1008): c = 1 + y/Lc, t = y%Lc
__global__ __launch_bounds__(256) void pass3_kernel(
    float* __restrict__ O, const float* __restrict__ carry,
    const float* __restrict__ Rpow)
{
    const int y  = blockIdx.y;
    const int c  = 1 + (y >> 4);
    const int t  = y & 15;
    const int bn = blockIdx.x * 64;
    const float* A = carry + (size_t)(c - 1) * ROWSZ;
    const float* P = Rpow + (size_t)t * SZ;            // R^{t+1}
    float acc[2][4] = {};
    core32(A, P, bn, acc);
    float* obase = O + (size_t)(Lc * c + t) * 512;
    epi32(acc, bn, obase, OROW, obase, OROW);
}

// ---------------------------------------------------------------------------
// Small copies / gathers
// ---------------------------------------------------------------------------
__global__ void copy_floats_kernel(float* __restrict__ dst,
                                   const float* __restrict__ src, int n4)
{
    int i = blockIdx.x * blockDim.x + threadIdx.x;
    if (i < n4) ((float4*)dst)[i] = ((const float4*)src)[i];
}

// U[g][0][b] = O[b, Lc*Jg*g + Lc-1, :]   (grid 256 = g*32+b, block 128)
__global__ void u0_gather_kernel(float* __restrict__ U, const float* __restrict__ O)
{
    const int row = blockIdx.x;
    const int g = row >> 5, b = row & 31;
    const float4* src = (const float4*)(O + ((size_t)b * Tn + (size_t)g * Jg * Lc + Lc - 1) * 512);
    float4* dst = (float4*)(U + (size_t)(g * Jg) * ROWSZ + (size_t)b * 512);
    dst[threadIdx.x] = src[threadIdx.x];
}

// ---------------------------------------------------------------------------
// Launch sequence — all stream-ordered, graph-capturable, no allocations.
// ---------------------------------------------------------------------------
extern "C" void kernel_launch(void* const* d_in, const int* in_sizes, int n_in,
                              void* d_out, int out_size)
{
    const float* x = (const float*)d_in[0];  // [B, T, D]
    const float* w = (const float*)d_in[1];  // [D, U]
    const float* r = (const float*)d_in[2];  // [U, U]
    float* o = (float*)d_out;                // [B, T, U]
    (void)in_sizes; (void)n_in; (void)out_size;

    float *Rpow, *Qpow, *U, *G, *carry;
    cudaGetSymbolAddress((void**)&Rpow,  g_Rpow);
    cudaGetSymbolAddress((void**)&Qpow,  g_Qpow);
    cudaGetSymbolAddress((void**)&U,     g_U);
    cudaGetSymbolAddress((void**)&G,     g_G);
    cudaGetSymbolAddress((void**)&carry, g_carry);

    // Phase A: O = X @ W
    gemm_nn_kernel<<<dim3(8, M / 64), 256>>>(x, w, o);

    // Phase B: power ladders.  R^1..R^16 then S^1..S^8 (S = R^16)
    copy_floats_kernel<<<(SZ / 4 + 255) / 256, 256>>>(Rpow, r, SZ / 4);
    for (int n = 1; n < Lc; n <<= 1)
        power_level_kernel<<<dim3(8, 8, n), 256>>>(Rpow, n);
    copy_floats_kernel<<<(SZ / 4 + 255) / 256, 256>>>(Qpow, Rpow + (size_t)(Lc - 1) * SZ, SZ / 4);
    for (int n = 1; n < Jg; n <<= 1)
        power_level_kernel<<<dim3(8, 8, n), 256>>>(Qpow, n);

    // Phase C: local scans (15 sequential batched steps)
    for (int t = 1; t < Lc; t++)
        pass1_step_kernel<<<dim3(8, 32), 256>>>(r, o, t);

    // Phase D: hierarchical carry scan
    u0_gather_kernel<<<Gg * Bn, 128>>>(U, o);
    for (int j = 1; j < Jg; j++)
        u_step_kernel<<<dim3(8, Gg), 256>>>(U, Rpow, o, j);
    copy_floats_kernel<<<(ROWSZ / 4 + 255) / 256, 256>>>(G, U + (size_t)(Jg - 1) * ROWSZ, ROWSZ / 4);
    for (int g = 1; g < Gg; g++)
        g_step_kernel<<<dim3(8), 256>>>(G, Qpow, U, g);
    // carry[0..Jg-1] = U[0][0..Jg-1]  (group 0 has no incoming carry)
    copy_floats_kernel<<<(Jg * ROWSZ / 4 + 255) / 256, 256>>>(carry, U, Jg * ROWSZ / 4);
    carry_batch_kernel<<<dim3(8, (Gg - 1) * Jg), 256>>>(carry, G, Qpow, U);

    // Phase E: batched correction (single fully-parallel launch)
    pass3_kernel<<<dim3(8, (Cc - 1) * Lc), 256>>>(o, carry, Rpow);
}

// round 5
// speedup vs baseline: 4.2537x; 1.0439x over previous
#include <cuda_runtime.h>

namespace {
constexpr int Bn = 32;      // batch
constexpr int Tn = 1024;    // time
constexpr int Dn = 512;     // dims (D == U)
constexpr int M  = Bn * Tn; // 32768

constexpr int Lc = 16;          // chunk length
constexpr int Cc = Tn / Lc;     // 64 chunks
constexpr int Gg = 8;           // carry-scan groups
constexpr int Jg = Cc / Gg;     // 8 chunks per group

constexpr int SZ    = 512 * 512;
constexpr int ROWSZ = 32 * 512;
constexpr size_t OROW = (size_t)Tn * Dn;

constexpr int BK = 16;
}

// ---------------------------------------------------------------------------
// Static device scratch
// ---------------------------------------------------------------------------
__device__ float g_Rpow[16 * SZ];   // R^1..R^16
__device__ float g_Qpow[8 * SZ];    // S^1..S^8, S = R^16
__device__ float g_U[Cc * ROWSZ];
__device__ float g_G[Gg * ROWSZ];
__device__ float g_carry[Cc * ROWSZ];

// ---------------------------------------------------------------------------
// 64x128 double-buffered core:  acc[4][8] += A(64x512 contiguous) @ B[:,bn:bn+128]
// 256 threads. Cols split as [bn+tx*4 .. +3] and [bn+64+tx*4 .. +3].
// ---------------------------------------------------------------------------
__device__ __forceinline__ void core64(const float* __restrict__ A,
                                       const float* __restrict__ Bm,
                                       int bn, float acc[4][8])
{
    __shared__ float As[2][BK][68];
    __shared__ float Bs[2][BK][128];
    const int tid  = threadIdx.x;
    const int tx   = tid & 15;
    const int ty   = tid >> 4;
    const int arow = tid >> 2;
    const int akq  = (tid & 3) << 2;
    const int brow = tid >> 4;
    const int bcol = (tid & 15) << 2;

    float4 av  = *(const float4*)(A + (size_t)arow * 512 + akq);
    float4 bv0 = *(const float4*)(Bm + (size_t)brow * 512 + bn + bcol);
    float4 bv1 = *(const float4*)(Bm + (size_t)brow * 512 + bn + bcol + 64);
    As[0][akq + 0][arow] = av.x;
    As[0][akq + 1][arow] = av.y;
    As[0][akq + 2][arow] = av.z;
    As[0][akq + 3][arow] = av.w;
    *(float4*)(&Bs[0][brow][bcol])      = bv0;
    *(float4*)(&Bs[0][brow][bcol + 64]) = bv1;
    __syncthreads();

    int cur = 0;
    for (int k0 = 0; k0 < 512; k0 += BK) {
        const bool more = (k0 + BK) < 512;
        if (more) {
            av  = *(const float4*)(A + (size_t)arow * 512 + k0 + BK + akq);
            bv0 = *(const float4*)(Bm + (size_t)(k0 + BK + brow) * 512 + bn + bcol);
            bv1 = *(const float4*)(Bm + (size_t)(k0 + BK + brow) * 512 + bn + bcol + 64);
        }
#pragma unroll
        for (int k = 0; k < BK; k++) {
            float4 a  = *(const float4*)(&As[cur][k][ty * 4]);
            float4 b0 = *(const float4*)(&Bs[cur][k][tx * 4]);
            float4 b1 = *(const float4*)(&Bs[cur][k][tx * 4 + 64]);
            float am[4] = {a.x, a.y, a.z, a.w};
#pragma unroll
            for (int i = 0; i < 4; i++) {
                acc[i][0] += am[i] * b0.x;
                acc[i][1] += am[i] * b0.y;
                acc[i][2] += am[i] * b0.z;
                acc[i][3] += am[i] * b0.w;
                acc[i][4] += am[i] * b1.x;
                acc[i][5] += am[i] * b1.y;
                acc[i][6] += am[i] * b1.z;
                acc[i][7] += am[i] * b1.w;
            }
        }
        if (more) {
            As[cur ^ 1][akq + 0][arow] = av.x;
            As[cur ^ 1][akq + 1][arow] = av.y;
            As[cur ^ 1][akq + 2][arow] = av.z;
            As[cur ^ 1][akq + 3][arow] = av.w;
            *(float4*)(&Bs[cur ^ 1][brow][bcol])      = bv0;
            *(float4*)(&Bs[cur ^ 1][brow][bcol + 64]) = bv1;
            __syncthreads();
            cur ^= 1;
        }
    }
}

// C = A @ B  (A contiguous rows). grid = (4, rows/64)
__global__ __launch_bounds__(256) void gemm_nn_kernel(
    const float* __restrict__ A, const float* __restrict__ B, float* __restrict__ C)
{
    const int bm = blockIdx.y * 64;
    const int bn = blockIdx.x * 128;
    float acc[4][8] = {};
    core64(A + (size_t)bm * 512, B, bn, acc);
    const int tx = threadIdx.x & 15, ty = threadIdx.x >> 4;
#pragma unroll
    for (int i = 0; i < 4; i++) {
        float* cptr = C + (size_t)(bm + ty * 4 + i) * 512 + bn;
        *(float4*)(cptr + tx * 4)      = make_float4(acc[i][0], acc[i][1], acc[i][2], acc[i][3]);
        *(float4*)(cptr + 64 + tx * 4) = make_float4(acc[i][4], acc[i][5], acc[i][6], acc[i][7]);
    }
}

// P[n+z] = P[z] @ P[n-1] for z = 0..n-1   (0-indexed: slot k holds R^{k+1})
__global__ __launch_bounds__(256) void power_level_kernel(float* __restrict__ P, int n)
{
    const int z  = blockIdx.z;
    const int bm = blockIdx.y * 64;
    const int bn = blockIdx.x * 128;
    float acc[4][8] = {};
    core64(P + (size_t)z * SZ + (size_t)bm * 512, P + (size_t)(n - 1) * SZ, bn, acc);
    float* C = P + (size_t)(n + z) * SZ;
    const int tx = threadIdx.x & 15, ty = threadIdx.x >> 4;
#pragma unroll
    for (int i = 0; i < 4; i++) {
        float* cptr = C + (size_t)(bm + ty * 4 + i) * 512 + bn;
        *(float4*)(cptr + tx * 4)      = make_float4(acc[i][0], acc[i][1], acc[i][2], acc[i][3]);
        *(float4*)(cptr + 64 + tx * 4) = make_float4(acc[i][4], acc[i][5], acc[i][6], acc[i][7]);
    }
}

// ---------------------------------------------------------------------------
// Pass 1 step t:  O[b, c*Lc+t, :] += O[b, c*Lc+t-1, :] @ R   (2048 rows)
// grid = (4, 32). Double-buffered, per-row A addressing.
// ---------------------------------------------------------------------------
__global__ __launch_bounds__(256) void pass1_step_kernel(
    const float* __restrict__ Rm, float* __restrict__ O, int t)
{
    __shared__ float As[2][BK][68];
    __shared__ float Bs[2][BK][128];
    const int bm  = blockIdx.y * 64;
    const int bn  = blockIdx.x * 128;
    const int tid = threadIdx.x;
    const int tx  = tid & 15;
    const int ty  = tid >> 4;
    const int arow = tid >> 2;
    const int akq  = (tid & 3) << 2;
    const int brow = tid >> 4;
    const int bcol = (tid & 15) << 2;

    const int ar = bm + arow;
    const float* abase = O + ((size_t)(ar & 31) * Tn + (size_t)(ar >> 5) * Lc + (t - 1)) * 512;

    float4 av  = *(const float4*)(abase + akq);
    float4 bv0 = *(const float4*)(Rm + (size_t)brow * 512 + bn + bcol);
    float4 bv1 = *(const float4*)(Rm + (size_t)brow * 512 + bn + bcol + 64);
    As[0][akq + 0][arow] = av.x;
    As[0][akq + 1][arow] = av.y;
    As[0][akq + 2][arow] = av.z;
    As[0][akq + 3][arow] = av.w;
    *(float4*)(&Bs[0][brow][bcol])      = bv0;
    *(float4*)(&Bs[0][brow][bcol + 64]) = bv1;
    __syncthreads();

    float acc[4][8] = {};
    int cur = 0;
    for (int k0 = 0; k0 < 512; k0 += BK) {
        const bool more = (k0 + BK) < 512;
        if (more) {
            av  = *(const float4*)(abase + k0 + BK + akq);
            bv0 = *(const float4*)(Rm + (size_t)(k0 + BK + brow) * 512 + bn + bcol);
            bv1 = *(const float4*)(Rm + (size_t)(k0 + BK + brow) * 512 + bn + bcol + 64);
        }
#pragma unroll
        for (int k = 0; k < BK; k++) {
            float4 a  = *(const float4*)(&As[cur][k][ty * 4]);
            float4 b0 = *(const float4*)(&Bs[cur][k][tx * 4]);
            float4 b1 = *(const float4*)(&Bs[cur][k][tx * 4 + 64]);
            float am[4] = {a.x, a.y, a.z, a.w};
#pragma unroll
            for (int i = 0; i < 4; i++) {
                acc[i][0] += am[i] * b0.x;
                acc[i][1] += am[i] * b0.y;
                acc[i][2] += am[i] * b0.z;
                acc[i][3] += am[i] * b0.w;
                acc[i][4] += am[i] * b1.x;
                acc[i][5] += am[i] * b1.y;
                acc[i][6] += am[i] * b1.z;
                acc[i][7] += am[i] * b1.w;
            }
        }
        if (more) {
            As[cur ^ 1][akq + 0][arow] = av.x;
            As[cur ^ 1][akq + 1][arow] = av.y;
            As[cur ^ 1][akq + 2][arow] = av.z;
            As[cur ^ 1][akq + 3][arow] = av.w;
            *(float4*)(&Bs[cur ^ 1][brow][bcol])      = bv0;
            *(float4*)(&Bs[cur ^ 1][brow][bcol + 64]) = bv1;
            __syncthreads();
            cur ^= 1;
        }
    }

#pragma unroll
    for (int i = 0; i < 4; i++) {
        const int row = bm + ty * 4 + i;
        float* optr = O + ((size_t)(row & 31) * Tn + (size_t)(row >> 5) * Lc + t) * 512 + bn;
        float4 e0 = *(const float4*)(optr + tx * 4);
        float4 e1 = *(const float4*)(optr + 64 + tx * 4);
        e0.x += acc[i][0]; e0.y += acc[i][1]; e0.z += acc[i][2]; e0.w += acc[i][3];
        e1.x += acc[i][4]; e1.y += acc[i][5]; e1.z += acc[i][6]; e1.w += acc[i][7];
        *(float4*)(optr + tx * 4)      = e0;
        *(float4*)(optr + 64 + tx * 4) = e1;
    }
}

// ---------------------------------------------------------------------------
// 32x128 double-buffered core:  acc[2][8] += A(32x512 contiguous) @ B[:,bn:bn+128]
// ---------------------------------------------------------------------------
__device__ __forceinline__ void core32(const float* __restrict__ A,
                                       const float* __restrict__ Bm,
                                       int bn, float acc[2][8])
{
    __shared__ float As[2][BK][34];
    __shared__ float Bs[2][BK][128];
    const int tid = threadIdx.x;
    const int tx  = tid & 15;
    const int ty  = tid >> 4;
    const int arow = (tid >> 2) & 31;
    const int akq  = (tid & 3) << 2;
    const int brow = tid >> 4;
    const int bcol = (tid & 15) << 2;
    const bool aload = tid < 128;

    float4 av = make_float4(0.f, 0.f, 0.f, 0.f);
    if (aload) av = *(const float4*)(A + (size_t)arow * 512 + akq);
    float4 bv0 = *(const float4*)(Bm + (size_t)brow * 512 + bn + bcol);
    float4 bv1 = *(const float4*)(Bm + (size_t)brow * 512 + bn + bcol + 64);
    if (aload) {
        As[0][akq + 0][arow] = av.x;
        As[0][akq + 1][arow] = av.y;
        As[0][akq + 2][arow] = av.z;
        As[0][akq + 3][arow] = av.w;
    }
    *(float4*)(&Bs[0][brow][bcol])      = bv0;
    *(float4*)(&Bs[0][brow][bcol + 64]) = bv1;
    __syncthreads();

    int cur = 0;
    for (int k0 = 0; k0 < 512; k0 += BK) {
        const bool more = (k0 + BK) < 512;
        if (more) {
            if (aload) av = *(const float4*)(A + (size_t)arow * 512 + k0 + BK + akq);
            bv0 = *(const float4*)(Bm + (size_t)(k0 + BK + brow) * 512 + bn + bcol);
            bv1 = *(const float4*)(Bm + (size_t)(k0 + BK + brow) * 512 + bn + bcol + 64);
        }
#pragma unroll
        for (int k = 0; k < BK; k++) {
            float2 a  = *(const float2*)(&As[cur][k][ty * 2]);
            float4 b0 = *(const float4*)(&Bs[cur][k][tx * 4]);
            float4 b1 = *(const float4*)(&Bs[cur][k][tx * 4 + 64]);
            float am[2] = {a.x, a.y};
#pragma unroll
            for (int i = 0; i < 2; i++) {
                acc[i][0] += am[i] * b0.x;
                acc[i][1] += am[i] * b0.y;
                acc[i][2] += am[i] * b0.z;
                acc[i][3] += am[i] * b0.w;
                acc[i][4] += am[i] * b1.x;
                acc[i][5] += am[i] * b1.y;
                acc[i][6] += am[i] * b1.z;
                acc[i][7] += am[i] * b1.w;
            }
        }
        if (more) {
            if (aload) {
                As[cur ^ 1][akq + 0][arow] = av.x;
                As[cur ^ 1][akq + 1][arow] = av.y;
                As[cur ^ 1][akq + 2][arow] = av.z;
                As[cur ^ 1][akq + 3][arow] = av.w;
            }
            *(float4*)(&Bs[cur ^ 1][brow][bcol])      = bv0;
            *(float4*)(&Bs[cur ^ 1][brow][bcol + 64]) = bv1;
            __syncthreads();
            cur ^= 1;
        }
    }
}

__device__ __forceinline__ void epi32(const float acc[2][8], int bn,
                                      const float* __restrict__ addB, size_t addS,
                                      float* __restrict__ outB, size_t outS)
{
    const int tx = threadIdx.x & 15, ty = threadIdx.x >> 4;
#pragma unroll
    for (int i = 0; i < 2; i++) {
        const int b = ty * 2 + i;
        const float* ap = addB + (size_t)b * addS + bn;
        float* op = outB + (size_t)b * outS + bn;
        float4 a0 = *(const float4*)(ap + tx * 4);
        float4 a1 = *(const float4*)(ap + 64 + tx * 4);
        *(float4*)(op + tx * 4) = make_float4(a0.x + acc[i][0], a0.y + acc[i][1],
                                              a0.z + acc[i][2], a0.w + acc[i][3]);
        *(float4*)(op + 64 + tx * 4) = make_float4(a1.x + acc[i][4], a1.y + acc[i][5],
                                                   a1.z + acc[i][6], a1.w + acc[i][7]);
    }
}

// u_{g,j} = last_{Jg*g+j} + u_{g,j-1} @ R^16    (grid (4, Gg))
__global__ __launch_bounds__(256) void u_step_kernel(
    float* __restrict__ U, const float* __restrict__ Rpow,
    const float* __restrict__ O, int j)
{
    const int g  = blockIdx.y;
    const int bn = blockIdx.x * 128;
    float acc[2][8] = {};
    core32(U + (size_t)(g * Jg + j - 1) * ROWSZ, Rpow + (size_t)(Lc - 1) * SZ, bn, acc);
    const int time = Lc * (Jg * g + j) + (Lc - 1);
    epi32(acc, bn, O + (size_t)time * 512, OROW, U + (size_t)(g * Jg + j) * ROWSZ, 512);
}

// G_g = U[g][Jg-1] + G_{g-1} @ S^Jg             (grid (4))
__global__ __launch_bounds__(256) void g_step_kernel(
    float* __restrict__ G, const float* __restrict__ Qpow,
    const float* __restrict__ U, int g)
{
    const int bn = blockIdx.x * 128;
    float acc[2][8] = {};
    core32(G + (size_t)(g - 1) * ROWSZ, Qpow + (size_t)(Jg - 1) * SZ, bn, acc);
    epi32(acc, bn, U + (size_t)(g * Jg + Jg - 1) * ROWSZ, 512, G + (size_t)g * ROWSZ, 512);
}

// carry_{Jg*g+j} = U[g][j] + G_{g-1} @ S^{j+1}  (grid (4, 56))
__global__ __launch_bounds__(256) void carry_batch_kernel(
    float* __restrict__ carry, const float* __restrict__ G,
    const float* __restrict__ Qpow, const float* __restrict__ U)
{
    const int y  = blockIdx.y;
    const int g  = 1 + (y >> 3);
    const int j  = y & 7;
    const int bn = blockIdx.x * 128;
    float acc[2][8] = {};
    core32(G + (size_t)(g - 1) * ROWSZ, Qpow + (size_t)j * SZ, bn, acc);
    epi32(acc, bn, U + (size_t)(g * Jg + j) * ROWSZ, 512,
          carry + (size_t)(g * Jg + j) * ROWSZ, 512);
}

// Pass 3 batched:  O[b, Lc*c+t, :] += carry_{c-1} @ R^{t+1}   (grid (4, 1008))
__global__ __launch_bounds__(256) void pass3_kernel(
    float* __restrict__ O, const float* __restrict__ carry,
    const float* __restrict__ Rpow)
{
    const int y  = blockIdx.y;
    const int c  = 1 + (y >> 4);
    const int t  = y & 15;
    const int bn = blockIdx.x * 128;
    float acc[2][8] = {};
    core32(carry + (size_t)(c - 1) * ROWSZ, Rpow + (size_t)t * SZ, bn, acc);
    float* obase = O + (size_t)(Lc * c + t) * 512;
    epi32(acc, bn, obase, OROW, obase, OROW);
}

// ---------------------------------------------------------------------------
// Small copies / gathers
// ---------------------------------------------------------------------------
__global__ void copy_floats_kernel(float* __restrict__ dst,
                                   const float* __restrict__ src, int n4)
{
    int i = blockIdx.x * blockDim.x + threadIdx.x;
    if (i < n4) ((float4*)dst)[i] = ((const float4*)src)[i];
}

__global__ void u0_gather_kernel(float* __restrict__ U, const float* __restrict__ O)
{
    const int row = blockIdx.x;
    const int g = row >> 5, b = row & 31;
    const float4* src = (const float4*)(O + ((size_t)b * Tn + (size_t)g * Jg * Lc + Lc - 1) * 512);
    float4* dst = (float4*)(U + (size_t)(g * Jg) * ROWSZ + (size_t)b * 512);
    dst[threadIdx.x] = src[threadIdx.x];
}

// ---------------------------------------------------------------------------
// Launch sequence
// ---------------------------------------------------------------------------
extern "C" void kernel_launch(void* const* d_in, const int* in_sizes, int n_in,
                              void* d_out, int out_size)
{
    const float* x = (const float*)d_in[0];
    const float* w = (const float*)d_in[1];
    const float* r = (const float*)d_in[2];
    float* o = (float*)d_out;
    (void)in_sizes; (void)n_in; (void)out_size;

    float *Rpow, *Qpow, *U, *G, *carry;
    cudaGetSymbolAddress((void**)&Rpow,  g_Rpow);
    cudaGetSymbolAddress((void**)&Qpow,  g_Qpow);
    cudaGetSymbolAddress((void**)&U,     g_U);
    cudaGetSymbolAddress((void**)&G,     g_G);
    cudaGetSymbolAddress((void**)&carry, g_carry);

    // Phase A: O = X @ W
    gemm_nn_kernel<<<dim3(4, M / 64), 256>>>(x, w, o);

    // Phase B: power ladders
    copy_floats_kernel<<<(SZ / 4 + 255) / 256, 256>>>(Rpow, r, SZ / 4);
    for (int n = 1; n < Lc; n <<= 1)
        power_level_kernel<<<dim3(4, 8, n), 256>>>(Rpow, n);
    copy_floats_kernel<<<(SZ / 4 + 255) / 256, 256>>>(Qpow, Rpow + (size_t)(Lc - 1) * SZ, SZ / 4);
    for (int n = 1; n < Jg; n <<= 1)
        power_level_kernel<<<dim3(4, 8, n), 256>>>(Qpow, n);

    // Phase C: local scans
    for (int t = 1; t < Lc; t++)
        pass1_step_kernel<<<dim3(4, 32), 256>>>(r, o, t);

    // Phase D: hierarchical carry scan
    u0_gather_kernel<<<Gg * Bn, 128>>>(U, o);
    for (int j = 1; j < Jg; j++)
        u_step_kernel<<<dim3(4, Gg), 256>>>(U, Rpow, o, j);
    copy_floats_kernel<<<(ROWSZ / 4 + 255) / 256, 256>>>(G, U + (size_t)(Jg - 1) * ROWSZ, ROWSZ / 4);
    for (int g = 1; g < Gg; g++)
        g_step_kernel<<<dim3(4), 256>>>(G, Qpow, U, g);
    copy_floats_kernel<<<(Jg * ROWSZ / 4 + 255) / 256, 256>>>(carry, U, Jg * ROWSZ / 4);
    carry_batch_kernel<<<dim3(4, (Gg - 1) * Jg), 256>>>(carry, G, Qpow, U);

    // Phase E: batched correction
    pass3_kernel<<<dim3(4, (Cc - 1) * Lc), 256>>>(o, carry, Rpow);
}

// round 7
// speedup vs baseline: 6.1911x; 1.4555x over previous
#include <cuda_runtime.h>
#include <cuda_bf16.h>
#include <cstdint>

namespace {
constexpr int Bn = 32;
constexpr int Tn = 1024;
constexpr int Dn = 512;
constexpr int M  = Bn * Tn;

constexpr int Lc = 16;
constexpr int Cc = Tn / Lc;     // 64
constexpr int Gg = 8;
constexpr int Jg = Cc / Gg;     // 8

constexpr int SZ    = 512 * 512;
constexpr int ROWSZ = 32 * 512;
constexpr size_t OROW = (size_t)Tn * Dn;

constexpr int BK  = 16;   // fp32 core k-tile
constexpr int AST = 20;   // hmma smem word stride (conflict-free for frag reads)
}

// ---------------------------------------------------------------------------
// Static device scratch
// ---------------------------------------------------------------------------
__device__ float g_Rpow[16 * SZ];   // R^1..R^16
__device__ float g_Qpow[8 * SZ];    // S^1..S^8, S = R^16
__device__ float g_U[Cc * ROWSZ];
__device__ float g_G[Gg * ROWSZ];
__device__ float g_carry[Cc * ROWSZ];

// ---------------------------------------------------------------------------
// bf16 split + mma.sync helpers
// ---------------------------------------------------------------------------
__device__ __forceinline__ uint32_t packbf(float a, float b) {
    uint32_t r;  // low half = a, high half = b
    asm("cvt.rn.bf16x2.f32 %0, %1, %2;" : "=r"(r) : "f"(b), "f"(a));
    return r;
}
__device__ __forceinline__ float lo_f(uint32_t p) { return __uint_as_float(p << 16); }
__device__ __forceinline__ float hi_f(uint32_t p) { return __uint_as_float(p & 0xFFFF0000u); }

__device__ __forceinline__ void mma16816(float* c, const uint32_t* a,
                                         uint32_t b0, uint32_t b1) {
    asm volatile(
        "mma.sync.aligned.m16n8k16.row.col.f32.bf16.bf16.f32 "
        "{%0,%1,%2,%3}, {%4,%5,%6,%7}, {%8,%9}, {%0,%1,%2,%3};"
        : "+f"(c[0]), "+f"(c[1]), "+f"(c[2]), "+f"(c[3])
        : "r"(a[0]), "r"(a[1]), "r"(a[2]), "r"(a[3]), "r"(b0), "r"(b1));
}

// ---------------------------------------------------------------------------
// HMMA core: acc[2][4][4] += A(128x512) @ B(512x512)[:, bn:bn+64]
// 256 threads, warps 4x2 -> each warp 32(m) x 32(n). K chunked by 32.
// Split bf16: 3 MMA terms (AhBh + AhBl + AlBh).
// arow: this thread's A staging ptr at (row = tid>>1, k = (tid&1)*16)
// bcol: this thread's B staging ptr at (k = (tid>>6)*8, n = bn + (tid&63))
// ---------------------------------------------------------------------------
__device__ __forceinline__ void hmma_core(const float* __restrict__ arow,
                                          const float* __restrict__ bcol,
                                          float acc[2][4][4])
{
    __shared__ uint32_t sAh[128 * AST], sAl[128 * AST];
    __shared__ uint32_t sBh[64 * AST],  sBl[64 * AST];

    const int tid  = threadIdx.x;
    const int lane = tid & 31, wid = tid >> 5;
    const int g = lane >> 2, qi = lane & 3;
    const int mo = (wid >> 1) * 32, no = (wid & 1) * 32;

    const int sarow = tid >> 1;          // A staging row 0..127
    const int sah   = (tid & 1) * 8;     // word offset 0 / 8
    const int sbn   = tid & 63;          // B staging n-row
    const int sbw   = (tid >> 6) * 4;    // word offset 0,4,8,12

    float a_pf[16], b_pf[8];
#pragma unroll
    for (int j = 0; j < 16; j += 4) {
        float4 v = *(const float4*)(arow + j);
        a_pf[j] = v.x; a_pf[j+1] = v.y; a_pf[j+2] = v.z; a_pf[j+3] = v.w;
    }
#pragma unroll
    for (int j = 0; j < 8; j++) b_pf[j] = bcol[(size_t)j * 512];

    for (int kc = 0; kc < 16; kc++) {
        // convert + store this chunk
#pragma unroll
        for (int j = 0; j < 16; j += 2) {
            uint32_t h = packbf(a_pf[j], a_pf[j + 1]);
            uint32_t l = packbf(a_pf[j] - lo_f(h), a_pf[j + 1] - hi_f(h));
            sAh[sarow * AST + sah + (j >> 1)] = h;
            sAl[sarow * AST + sah + (j >> 1)] = l;
        }
#pragma unroll
        for (int j = 0; j < 8; j += 2) {
            uint32_t h = packbf(b_pf[j], b_pf[j + 1]);
            uint32_t l = packbf(b_pf[j] - lo_f(h), b_pf[j + 1] - hi_f(h));
            sBh[sbn * AST + sbw + (j >> 1)] = h;
            sBl[sbn * AST + sbw + (j >> 1)] = l;
        }
        __syncthreads();

        // prefetch next chunk
        if (kc < 15) {
            const float* ap = arow + (kc + 1) * 32;
#pragma unroll
            for (int j = 0; j < 16; j += 4) {
                float4 v = *(const float4*)(ap + j);
                a_pf[j] = v.x; a_pf[j+1] = v.y; a_pf[j+2] = v.z; a_pf[j+3] = v.w;
            }
            const float* bp = bcol + (size_t)(kc + 1) * 32 * 512;
#pragma unroll
            for (int j = 0; j < 8; j++) b_pf[j] = bp[(size_t)j * 512];
        }

        // compute: two k16 sub-steps
#pragma unroll
        for (int s = 0; s < 2; s++) {
            const int ws = s * 8;
            uint32_t aH[2][4], aL[2][4];
#pragma unroll
            for (int mf = 0; mf < 2; mf++) {
                const int r0 = mo + mf * 16 + g;
                aH[mf][0] = sAh[r0 * AST + ws + qi];
                aH[mf][1] = sAh[(r0 + 8) * AST + ws + qi];
                aH[mf][2] = sAh[r0 * AST + ws + qi + 4];
                aH[mf][3] = sAh[(r0 + 8) * AST + ws + qi + 4];
                aL[mf][0] = sAl[r0 * AST + ws + qi];
                aL[mf][1] = sAl[(r0 + 8) * AST + ws + qi];
                aL[mf][2] = sAl[r0 * AST + ws + qi + 4];
                aL[mf][3] = sAl[(r0 + 8) * AST + ws + qi + 4];
            }
#pragma unroll
            for (int f = 0; f < 4; f++) {
                const int nr = no + f * 8 + g;
                uint32_t bh0 = sBh[nr * AST + ws + qi];
                uint32_t bh1 = sBh[nr * AST + ws + qi + 4];
                uint32_t bl0 = sBl[nr * AST + ws + qi];
                uint32_t bl1 = sBl[nr * AST + ws + qi + 4];
#pragma unroll
                for (int mf = 0; mf < 2; mf++) {
                    mma16816(acc[mf][f], aH[mf], bh0, bh1);
                    mma16816(acc[mf][f], aH[mf], bl0, bl1);
                    mma16816(acc[mf][f], aL[mf], bh0, bh1);
                }
            }
        }
        __syncthreads();
    }
}

// ---------------------------------------------------------------------------
// HMMA kernels
// ---------------------------------------------------------------------------
// C = A @ B.  grid (x: n/64, y: m/128, z: batch)
__global__ __launch_bounds__(256, 2) void hmma_gemm(
    const float* __restrict__ A, const float* __restrict__ B,
    float* __restrict__ C, long long az, long long cz)
{
    const int z  = blockIdx.z;
    const int bn = blockIdx.x * 64;
    const int bm = blockIdx.y * 128;
    const int tid = threadIdx.x;
    const float* arow = A + (size_t)z * az + (size_t)(bm + (tid >> 1)) * 512 + (tid & 1) * 16;
    const float* bcol = B + (size_t)((tid >> 6) * 8) * 512 + bn + (tid & 63);
    float acc[2][4][4] = {};
    hmma_core(arow, bcol, acc);

    const int lane = tid & 31, wid = tid >> 5;
    const int g = lane >> 2, qi = lane & 3;
    const int mo = (wid >> 1) * 32, no = (wid & 1) * 32;
    float* Cz = C + (size_t)z * cz;
#pragma unroll
    for (int mf = 0; mf < 2; mf++) {
#pragma unroll
        for (int f = 0; f < 4; f++) {
            const int r0  = bm + mo + mf * 16 + g;
            const int col = bn + no + f * 8 + 2 * qi;
            *(float2*)(Cz + (size_t)r0 * 512 + col) =
                make_float2(acc[mf][f][0], acc[mf][f][1]);
            *(float2*)(Cz + (size_t)(r0 + 8) * 512 + col) =
                make_float2(acc[mf][f][2], acc[mf][f][3]);
        }
    }
}

// pass1 step t: O[b, c*16+t, :] += O[b, c*16+t-1, :] @ R.  grid (8, 16)
__global__ __launch_bounds__(256, 2) void hmma_pass1(
    const float* __restrict__ Rm, float* __restrict__ O, int t)
{
    const int bn = blockIdx.x * 64;
    const int bm = blockIdx.y * 128;
    const int tid = threadIdx.x;
    const int srow = bm + (tid >> 1);
    const float* arow = O + ((size_t)(srow & 31) * Tn + (size_t)(srow >> 5) * Lc + (t - 1)) * 512
                        + (tid & 1) * 16;
    const float* bcol = Rm + (size_t)((tid >> 6) * 8) * 512 + bn + (tid & 63);
    float acc[2][4][4] = {};
    hmma_core(arow, bcol, acc);

    const int lane = tid & 31, wid = tid >> 5;
    const int g = lane >> 2, qi = lane & 3;
    const int mo = (wid >> 1) * 32, no = (wid & 1) * 32;
#pragma unroll
    for (int mf = 0; mf < 2; mf++) {
#pragma unroll
        for (int f = 0; f < 4; f++) {
            const int col = bn + no + f * 8 + 2 * qi;
#pragma unroll
            for (int h = 0; h < 2; h++) {
                const int r = bm + mo + mf * 16 + g + h * 8;
                float* op = O + ((size_t)(r & 31) * Tn + (size_t)(r >> 5) * Lc + t) * 512 + col;
                float2 e = *(float2*)op;
                e.x += acc[mf][f][2 * h];
                e.y += acc[mf][f][2 * h + 1];
                *(float2*)op = e;
            }
        }
    }
}

// pass3: O[b, 16*(c+1)+t, :] += carry[c] @ R^{t+1}.  grid (8, 16, 16)
__global__ __launch_bounds__(256, 2) void hmma_pass3(
    float* __restrict__ O, const float* __restrict__ carry,
    const float* __restrict__ Rpow)
{
    const int t  = blockIdx.z;
    const int bn = blockIdx.x * 64;
    const int bm = blockIdx.y * 128;
    const int tid = threadIdx.x;
    const float* arow = carry + (size_t)(bm + (tid >> 1)) * 512 + (tid & 1) * 16;
    const float* bcol = Rpow + (size_t)t * SZ + (size_t)((tid >> 6) * 8) * 512 + bn + (tid & 63);
    float acc[2][4][4] = {};
    hmma_core(arow, bcol, acc);

    const int lane = tid & 31, wid = tid >> 5;
    const int g = lane >> 2, qi = lane & 3;
    const int mo = (wid >> 1) * 32, no = (wid & 1) * 32;
#pragma unroll
    for (int mf = 0; mf < 2; mf++) {
#pragma unroll
        for (int f = 0; f < 4; f++) {
            const int col = bn + no + f * 8 + 2 * qi;
#pragma unroll
            for (int h = 0; h < 2; h++) {
                const int r = bm + mo + mf * 16 + g + h * 8;
                const int cidx = r >> 5;
                if (cidx < Cc - 1) {
                    const int b = r & 31;
                    float* op = O + ((size_t)b * Tn + (size_t)(cidx + 1) * Lc + t) * 512 + col;
                    float2 e = *(float2*)op;
                    e.x += acc[mf][f][2 * h];
                    e.y += acc[mf][f][2 * h + 1];
                    *(float2*)op = e;
                }
            }
        }
    }
}

// ---------------------------------------------------------------------------
// fp32 SIMT 32-row core (phase D) — unchanged from round 5
// ---------------------------------------------------------------------------
__device__ __forceinline__ void core32(const float* __restrict__ A,
                                       const float* __restrict__ Bm,
                                       int bn, float acc[2][8])
{
    __shared__ float As[2][BK][34];
    __shared__ float Bs[2][BK][128];
    const int tid = threadIdx.x;
    const int tx  = tid & 15;
    const int ty  = tid >> 4;
    const int arow = (tid >> 2) & 31;
    const int akq  = (tid & 3) << 2;
    const int brow = tid >> 4;
    const int bcol = (tid & 15) << 2;
    const bool aload = tid < 128;

    float4 av = make_float4(0.f, 0.f, 0.f, 0.f);
    if (aload) av = *(const float4*)(A + (size_t)arow * 512 + akq);
    float4 bv0 = *(const float4*)(Bm + (size_t)brow * 512 + bn + bcol);
    float4 bv1 = *(const float4*)(Bm + (size_t)brow * 512 + bn + bcol + 64);
    if (aload) {
        As[0][akq + 0][arow] = av.x;
        As[0][akq + 1][arow] = av.y;
        As[0][akq + 2][arow] = av.z;
        As[0][akq + 3][arow] = av.w;
    }
    *(float4*)(&Bs[0][brow][bcol])      = bv0;
    *(float4*)(&Bs[0][brow][bcol + 64]) = bv1;
    __syncthreads();

    int cur = 0;
    for (int k0 = 0; k0 < 512; k0 += BK) {
        const bool more = (k0 + BK) < 512;
        if (more) {
            if (aload) av = *(const float4*)(A + (size_t)arow * 512 + k0 + BK + akq);
            bv0 = *(const float4*)(Bm + (size_t)(k0 + BK + brow) * 512 + bn + bcol);
            bv1 = *(const float4*)(Bm + (size_t)(k0 + BK + brow) * 512 + bn + bcol + 64);
        }
#pragma unroll
        for (int k = 0; k < BK; k++) {
            float2 a  = *(const float2*)(&As[cur][k][ty * 2]);
            float4 b0 = *(const float4*)(&Bs[cur][k][tx * 4]);
            float4 b1 = *(const float4*)(&Bs[cur][k][tx * 4 + 64]);
            float am[2] = {a.x, a.y};
#pragma unroll
            for (int i = 0; i < 2; i++) {
                acc[i][0] += am[i] * b0.x;
                acc[i][1] += am[i] * b0.y;
                acc[i][2] += am[i] * b0.z;
                acc[i][3] += am[i] * b0.w;
                acc[i][4] += am[i] * b1.x;
                acc[i][5] += am[i] * b1.y;
                acc[i][6] += am[i] * b1.z;
                acc[i][7] += am[i] * b1.w;
            }
        }
        if (more) {
            if (aload) {
                As[cur ^ 1][akq + 0][arow] = av.x;
                As[cur ^ 1][akq + 1][arow] = av.y;
                As[cur ^ 1][akq + 2][arow] = av.z;
                As[cur ^ 1][akq + 3][arow] = av.w;
            }
            *(float4*)(&Bs[cur ^ 1][brow][bcol])      = bv0;
            *(float4*)(&Bs[cur ^ 1][brow][bcol + 64]) = bv1;
            __syncthreads();
            cur ^= 1;
        }
    }
}

__device__ __forceinline__ void epi32(const float acc[2][8], int bn,
                                      const float* __restrict__ addB, size_t addS,
                                      float* __restrict__ outB, size_t outS)
{
    const int tx = threadIdx.x & 15, ty = threadIdx.x >> 4;
#pragma unroll
    for (int i = 0; i < 2; i++) {
        const int b = ty * 2 + i;
        const float* ap = addB + (size_t)b * addS + bn;
        float* op = outB + (size_t)b * outS + bn;
        float4 a0 = *(const float4*)(ap + tx * 4);
        float4 a1 = *(const float4*)(ap + 64 + tx * 4);
        *(float4*)(op + tx * 4) = make_float4(a0.x + acc[i][0], a0.y + acc[i][1],
                                              a0.z + acc[i][2], a0.w + acc[i][3]);
        *(float4*)(op + 64 + tx * 4) = make_float4(a1.x + acc[i][4], a1.y + acc[i][5],
                                                   a1.z + acc[i][6], a1.w + acc[i][7]);
    }
}

__global__ __launch_bounds__(256) void u_step_kernel(
    float* __restrict__ U, const float* __restrict__ Rpow,
    const float* __restrict__ O, int j)
{
    const int g  = blockIdx.y;
    const int bn = blockIdx.x * 128;
    float acc[2][8] = {};
    core32(U + (size_t)(g * Jg + j - 1) * ROWSZ, Rpow + (size_t)(Lc - 1) * SZ, bn, acc);
    const int time = Lc * (Jg * g + j) + (Lc - 1);
    epi32(acc, bn, O + (size_t)time * 512, OROW, U + (size_t)(g * Jg + j) * ROWSZ, 512);
}

__global__ __launch_bounds__(256) void g_step_kernel(
    float* __restrict__ G, const float* __restrict__ Qpow,
    const float* __restrict__ U, int g)
{
    const int bn = blockIdx.x * 128;
    float acc[2][8] = {};
    core32(G + (size_t)(g - 1) * ROWSZ, Qpow + (size_t)(Jg - 1) * SZ, bn, acc);
    epi32(acc, bn, U + (size_t)(g * Jg + Jg - 1) * ROWSZ, 512, G + (size_t)g * ROWSZ, 512);
}

__global__ __launch_bounds__(256) void carry_batch_kernel(
    float* __restrict__ carry, const float* __restrict__ G,
    const float* __restrict__ Qpow, const float* __restrict__ U)
{
    const int y  = blockIdx.y;
    const int g  = 1 + (y >> 3);
    const int j  = y & 7;
    const int bn = blockIdx.x * 128;
    float acc[2][8] = {};
    core32(G + (size_t)(g - 1) * ROWSZ, Qpow + (size_t)j * SZ, bn, acc);
    epi32(acc, bn, U + (size_t)(g * Jg + j) * ROWSZ, 512,
          carry + (size_t)(g * Jg + j) * ROWSZ, 512);
}

// ---------------------------------------------------------------------------
// Small copies / gathers
// ---------------------------------------------------------------------------
__global__ void copy_floats_kernel(float* __restrict__ dst,
                                   const float* __restrict__ src, int n4)
{
    int i = blockIdx.x * blockDim.x + threadIdx.x;
    if (i < n4) ((float4*)dst)[i] = ((const float4*)src)[i];
}

__global__ void u0_gather_kernel(float* __restrict__ U, const float* __restrict__ O)
{
    const int row = blockIdx.x;
    const int g = row >> 5, b = row & 31;
    const float4* src = (const float4*)(O + ((size_t)b * Tn + (size_t)g * Jg * Lc + Lc - 1) * 512);
    float4* dst = (float4*)(U + (size_t)(g * Jg) * ROWSZ + (size_t)b * 512);
    dst[threadIdx.x] = src[threadIdx.x];
}

// ---------------------------------------------------------------------------
// Launch sequence
// ---------------------------------------------------------------------------
extern "C" void kernel_launch(void* const* d_in, const int* in_sizes, int n_in,
                              void* d_out, int out_size)
{
    const float* x = (const float*)d_in[0];
    const float* w = (const float*)d_in[1];
    const float* r = (const float*)d_in[2];
    float* o = (float*)d_out;
    (void)in_sizes; (void)n_in; (void)out_size;

    float *Rpow, *Qpow, *U, *G, *carry;
    cudaGetSymbolAddress((void**)&Rpow,  g_Rpow);
    cudaGetSymbolAddress((void**)&Qpow,  g_Qpow);
    cudaGetSymbolAddress((void**)&U,     g_U);
    cudaGetSymbolAddress((void**)&G,     g_G);
    cudaGetSymbolAddress((void**)&carry, g_carry);

    // Phase A: O = X @ W   (HMMA)
    hmma_gemm<<<dim3(8, M / 128, 1), 256>>>(x, w, o, 0, 0);

    // Phase B: power ladders (HMMA)
    copy_floats_kernel<<<(SZ / 4 + 255) / 256, 256>>>(Rpow, r, SZ / 4);
    for (int n = 1; n < Lc; n <<= 1)
        hmma_gemm<<<dim3(8, 4, n), 256>>>(
            Rpow, Rpow + (size_t)(n - 1) * SZ, Rpow + (size_t)n * SZ, SZ, SZ);
    copy_floats_kernel<<<(SZ / 4 + 255) / 256, 256>>>(Qpow, Rpow + (size_t)(Lc - 1) * SZ, SZ / 4);
    for (int n = 1; n < Jg; n <<= 1)
        hmma_gemm<<<dim3(8, 4, n), 256>>>(
            Qpow, Qpow + (size_t)(n - 1) * SZ, Qpow + (size_t)n * SZ, SZ, SZ);

    // Phase C: local scans (HMMA), 15 sequential steps
    for (int t = 1; t < Lc; t++)
        hmma_pass1<<<dim3(8, 16), 256>>>(r, o, t);

    // Phase D: hierarchical carry scan (fp32 SIMT)
    u0_gather_kernel<<<Gg * Bn, 128>>>(U, o);
    for (int j = 1; j < Jg; j++)
        u_step_kernel<<<dim3(4, Gg), 256>>>(U, Rpow, o, j);
    copy_floats_kernel<<<(ROWSZ / 4 + 255) / 256, 256>>>(G, U + (size_t)(Jg - 1) * ROWSZ, ROWSZ / 4);
    for (int g = 1; g < Gg; g++)
        g_step_kernel<<<dim3(4), 256>>>(G, Qpow, U, g);
    copy_floats_kernel<<<(Jg * ROWSZ / 4 + 255) / 256, 256>>>(carry, U, Jg * ROWSZ / 4);
    carry_batch_kernel<<<dim3(4, (Gg - 1) * Jg), 256>>>(carry, G, Qpow, U);

    // Phase E: batched correction (HMMA)
    hmma_pass3<<<dim3(8, 16, 16), 256>>>(o, carry, Rpow);
}

// round 8
// speedup vs baseline: 8.4817x; 1.3700x over previous
#include <cuda_runtime.h>
#include <cuda_bf16.h>
#include <cstdint>

namespace {
constexpr int Bn = 32;
constexpr int Tn = 1024;
constexpr int M  = Bn * Tn;

constexpr int Lc = 16;
constexpr int Cc = Tn / Lc;         // 64
constexpr size_t OROW = (size_t)Tn * 512;

constexpr int SZ  = 512 * 512;      // fp32 elements per matrix
constexpr int SZW = 256 * 512;      // packed bf16x2 words per matrix
constexpr int WST = 20;             // smem row stride in words (16 + pad, 16B-aligned rows)
constexpr int BUFW = 7680;          // words per stage buffer (Ah 2560 | Al 2560 | Bh 1280 | Bl 1280)
constexpr int SMEM_BYTES = 2 * BUFW * 4;   // 61440
}

// ---------------------------------------------------------------------------
// Static device scratch
// ---------------------------------------------------------------------------
__device__ float    g_Rf[16 * SZ];      // R^1..R^16 fp32 (ladder A operands)
__device__ uint32_t g_Rh[16 * SZW];     // packed bf16 hi of R^1..R^16
__device__ uint32_t g_Rl[16 * SZW];     // packed bf16 lo
__device__ float    g_Sf[5 * SZ];       // S^2,S^4,S^8,S^16,S^32 fp32 (S = R^16)
__device__ uint32_t g_Sh[5 * SZW];
__device__ uint32_t g_Sl[5 * SZW];
__device__ uint32_t g_Wh[SZW];          // packed W
__device__ uint32_t g_Wl[SZW];
__device__ float    g_V0[Cc * Bn * 512];
__device__ float    g_V1[Cc * Bn * 512];

// ---------------------------------------------------------------------------
// helpers
// ---------------------------------------------------------------------------
__device__ __forceinline__ uint32_t packbf(float a, float b) {
    uint32_t r;  // low half = a, high half = b
    asm("cvt.rn.bf16x2.f32 %0, %1, %2;" : "=r"(r) : "f"(b), "f"(a));
    return r;
}
__device__ __forceinline__ float lo_f(uint32_t p) { return __uint_as_float(p << 16); }
__device__ __forceinline__ float hi_f(uint32_t p) { return __uint_as_float(p & 0xFFFF0000u); }

__device__ __forceinline__ void mma16816(float* c, const uint32_t* a,
                                         uint32_t b0, uint32_t b1) {
    asm volatile(
        "mma.sync.aligned.m16n8k16.row.col.f32.bf16.bf16.f32 "
        "{%0,%1,%2,%3}, {%4,%5,%6,%7}, {%8,%9}, {%0,%1,%2,%3};"
        : "+f"(c[0]), "+f"(c[1]), "+f"(c[2]), "+f"(c[3])
        : "r"(a[0]), "r"(a[1]), "r"(a[2]), "r"(a[3]), "r"(b0), "r"(b1));
}

// ---------------------------------------------------------------------------
// Double-buffered HMMA core.
//   acc[2][4][4] += A(128x512 fp32, converted in-kernel) @ B(packed bf16 hi/lo)
// 256 threads, warps 4x2 -> 32x32 per warp. K chunked by 32 (16 chunks).
// arow: thread A ptr (row = tid>>1, k-offset (tid&1)*16)
// bh/bl: packed B base + bn + (tid&63); word (w,n) at offset w*512.
// ---------------------------------------------------------------------------
__device__ __forceinline__ void hmma_core_bb(const float* __restrict__ arow,
                                             const uint32_t* __restrict__ bh,
                                             const uint32_t* __restrict__ bl,
                                             float acc[2][4][4])
{
    extern __shared__ uint32_t sw[];
    const int tid  = threadIdx.x;
    const int lane = tid & 31, wid = tid >> 5;
    const int g = lane >> 2, qi = lane & 3;
    const int mo = (wid >> 1) * 32, no = (wid & 1) * 32;

    const int sar = tid >> 1;          // A staging row
    const int saw = (tid & 1) * 8;     // A word base (0 / 8)
    const int sbw = (tid >> 6) * 4;    // B word base (0,4,8,12)

    float af[16];
    uint32_t bhw[4], blw[4];

    auto LOAD = [&](int kc) {
        const float* ap = arow + kc * 32;
        float4 v;
        v = *(const float4*)(ap + 0);  af[0] = v.x;  af[1] = v.y;  af[2] = v.z;  af[3] = v.w;
        v = *(const float4*)(ap + 4);  af[4] = v.x;  af[5] = v.y;  af[6] = v.z;  af[7] = v.w;
        v = *(const float4*)(ap + 8);  af[8] = v.x;  af[9] = v.y;  af[10] = v.z; af[11] = v.w;
        v = *(const float4*)(ap + 12); af[12] = v.x; af[13] = v.y; af[14] = v.z; af[15] = v.w;
        const int off = (kc * 16 + sbw) * 512;
        bhw[0] = bh[off];        bhw[1] = bh[off + 512];
        bhw[2] = bh[off + 1024]; bhw[3] = bh[off + 1536];
        blw[0] = bl[off];        blw[1] = bl[off + 512];
        blw[2] = bl[off + 1024]; blw[3] = bl[off + 1536];
    };

    auto STORE = [&](int bi) {
        uint32_t h[8], l[8];
#pragma unroll
        for (int j = 0; j < 8; j++) {
            h[j] = packbf(af[2 * j], af[2 * j + 1]);
            l[j] = packbf(af[2 * j] - lo_f(h[j]), af[2 * j + 1] - hi_f(h[j]));
        }
        uint32_t* pA = sw + bi * BUFW + sar * WST + saw;
        *(uint4*)pA        = make_uint4(h[0], h[1], h[2], h[3]);
        *(uint4*)(pA + 4)  = make_uint4(h[4], h[5], h[6], h[7]);
        uint32_t* pAl = pA + 2560;
        *(uint4*)pAl       = make_uint4(l[0], l[1], l[2], l[3]);
        *(uint4*)(pAl + 4) = make_uint4(l[4], l[5], l[6], l[7]);
        uint32_t* pB = sw + bi * BUFW + 5120 + (tid & 63) * WST + sbw;
        *(uint4*)pB          = make_uint4(bhw[0], bhw[1], bhw[2], bhw[3]);
        *(uint4*)(pB + 1280) = make_uint4(blw[0], blw[1], blw[2], blw[3]);
    };

    auto COMPUTE = [&](int bi) {
        const uint32_t* bAh = sw + bi * BUFW;
        const uint32_t* bAl = bAh + 2560;
        const uint32_t* bBh = bAh + 5120;
        const uint32_t* bBl = bAh + 6400;
#pragma unroll
        for (int s = 0; s < 2; s++) {
            const int ws = s * 8;
            uint32_t aH[2][4], aL[2][4];
#pragma unroll
            for (int mf = 0; mf < 2; mf++) {
                const int r0 = mo + mf * 16 + g;
                aH[mf][0] = bAh[r0 * WST + ws + qi];
                aH[mf][1] = bAh[(r0 + 8) * WST + ws + qi];
                aH[mf][2] = bAh[r0 * WST + ws + qi + 4];
                aH[mf][3] = bAh[(r0 + 8) * WST + ws + qi + 4];
                aL[mf][0] = bAl[r0 * WST + ws + qi];
                aL[mf][1] = bAl[(r0 + 8) * WST + ws + qi];
                aL[mf][2] = bAl[r0 * WST + ws + qi + 4];
                aL[mf][3] = bAl[(r0 + 8) * WST + ws + qi + 4];
            }
#pragma unroll
            for (int f = 0; f < 4; f++) {
                const int nr = no + f * 8 + g;
                uint32_t bh0 = bBh[nr * WST + ws + qi];
                uint32_t bh1 = bBh[nr * WST + ws + qi + 4];
                uint32_t bl0 = bBl[nr * WST + ws + qi];
                uint32_t bl1 = bBl[nr * WST + ws + qi + 4];
#pragma unroll
                for (int mf = 0; mf < 2; mf++) {
                    mma16816(acc[mf][f], aH[mf], bh0, bh1);
                    mma16816(acc[mf][f], aH[mf], bl0, bl1);
                    mma16816(acc[mf][f], aL[mf], bh0, bh1);
                }
            }
        }
    };

    LOAD(0);
    STORE(0);
    __syncthreads();
    int cur = 0;
    for (int kc = 0; kc < 16; kc++) {
        if (kc < 15) LOAD(kc + 1);
        COMPUTE(cur);
        if (kc < 15) {
            STORE(cur ^ 1);
            __syncthreads();
            cur ^= 1;
        }
    }
}

// ---------------------------------------------------------------------------
// Kernels
// ---------------------------------------------------------------------------
// generic C = A @ B.  grid (n/64, m/128, z)
__global__ __launch_bounds__(256, 2) void hmma_gemm_bb(
    const float* __restrict__ A, const uint32_t* __restrict__ Bh,
    const uint32_t* __restrict__ Bl, float* __restrict__ C,
    long long az, long long bz, long long cz)
{
    const int z  = blockIdx.z;
    const int bn = blockIdx.x * 64;
    const int bm = blockIdx.y * 128;
    const int tid = threadIdx.x;
    const float* arow = A + (size_t)z * az + (size_t)(bm + (tid >> 1)) * 512 + (tid & 1) * 16;
    const uint32_t* bh = Bh + (size_t)z * bz + bn + (tid & 63);
    const uint32_t* bl = Bl + (size_t)z * bz + bn + (tid & 63);
    float acc[2][4][4] = {};
    hmma_core_bb(arow, bh, bl, acc);

    const int lane = tid & 31, wid = tid >> 5;
    const int g = lane >> 2, qi = lane & 3;
    const int mo = (wid >> 1) * 32, no = (wid & 1) * 32;
    float* Cz = C + (size_t)z * cz;
#pragma unroll
    for (int mf = 0; mf < 2; mf++)
#pragma unroll
        for (int f = 0; f < 4; f++) {
            const int r0  = bm + mo + mf * 16 + g;
            const int col = bn + no + f * 8 + 2 * qi;
            *(float2*)(Cz + (size_t)r0 * 512 + col) =
                make_float2(acc[mf][f][0], acc[mf][f][1]);
            *(float2*)(Cz + (size_t)(r0 + 8) * 512 + col) =
                make_float2(acc[mf][f][2], acc[mf][f][3]);
        }
}

// pass1 step t: O[b, c*16+t, :] += O[b, c*16+t-1, :] @ R.  grid (8, 16)
__global__ __launch_bounds__(256, 2) void hmma_pass1_bb(
    const uint32_t* __restrict__ Rh, const uint32_t* __restrict__ Rl,
    float* __restrict__ O, int t)
{
    const int bn = blockIdx.x * 64;
    const int bm = blockIdx.y * 128;
    const int tid = threadIdx.x;
    const int srow = bm + (tid >> 1);
    const float* arow = O + ((size_t)(srow & 31) * Tn + (size_t)(srow >> 5) * Lc + (t - 1)) * 512
                        + (tid & 1) * 16;
    const uint32_t* bh = Rh + bn + (tid & 63);
    const uint32_t* bl = Rl + bn + (tid & 63);
    float acc[2][4][4] = {};
    hmma_core_bb(arow, bh, bl, acc);

    const int lane = tid & 31, wid = tid >> 5;
    const int g = lane >> 2, qi = lane & 3;
    const int mo = (wid >> 1) * 32, no = (wid & 1) * 32;
#pragma unroll
    for (int mf = 0; mf < 2; mf++)
#pragma unroll
        for (int f = 0; f < 4; f++) {
            const int col = bn + no + f * 8 + 2 * qi;
#pragma unroll
            for (int h = 0; h < 2; h++) {
                const int r = bm + mo + mf * 16 + g + h * 8;
                float* op = O + ((size_t)(r & 31) * Tn + (size_t)(r >> 5) * Lc + t) * 512 + col;
                float2 e = *(float2*)op;
                e.x += acc[mf][f][2 * h];
                e.y += acc[mf][f][2 * h + 1];
                *(float2*)op = e;
            }
        }
}

// Hillis-Steele scan step: Vout[c] = Vin[c] + (c>=d ? Vin[c-d] @ S^d : 0).  grid (8, 16)
__global__ __launch_bounds__(256, 2) void hmma_scan_step(
    float* __restrict__ Vout, const float* __restrict__ Vin,
    const uint32_t* __restrict__ Sh, const uint32_t* __restrict__ Sl, int d)
{
    const int bn = blockIdx.x * 64;
    const int bm = blockIdx.y * 128;
    const int tid = threadIdx.x;
    const int srow = bm + (tid >> 1);
    const int csrc = (srow >> 5) - d;
    const int asrc = (csrc >= 0) ? (csrc * 32 + (srow & 31)) : srow;
    const float* arow = Vin + (size_t)asrc * 512 + (tid & 1) * 16;
    const uint32_t* bh = Sh + bn + (tid & 63);
    const uint32_t* bl = Sl + bn + (tid & 63);
    float acc[2][4][4] = {};
    hmma_core_bb(arow, bh, bl, acc);

    const int lane = tid & 31, wid = tid >> 5;
    const int g = lane >> 2, qi = lane & 3;
    const int mo = (wid >> 1) * 32, no = (wid & 1) * 32;
#pragma unroll
    for (int mf = 0; mf < 2; mf++)
#pragma unroll
        for (int f = 0; f < 4; f++) {
            const int col = bn + no + f * 8 + 2 * qi;
#pragma unroll
            for (int h = 0; h < 2; h++) {
                const int r = bm + mo + mf * 16 + g + h * 8;
                float2 e = *(const float2*)(Vin + (size_t)r * 512 + col);
                if ((r >> 5) >= d) {
                    e.x += acc[mf][f][2 * h];
                    e.y += acc[mf][f][2 * h + 1];
                }
                *(float2*)(Vout + (size_t)r * 512 + col) = e;
            }
        }
}

// pass3: O[b, 16*(c+1)+t, :] += V[c] @ R^{t+1}.  grid (8, 16, 16: t)
__global__ __launch_bounds__(256, 2) void hmma_pass3_bb(
    float* __restrict__ O, const float* __restrict__ V,
    const uint32_t* __restrict__ Rh, const uint32_t* __restrict__ Rl)
{
    const int t  = blockIdx.z;
    const int bn = blockIdx.x * 64;
    const int bm = blockIdx.y * 128;
    const int tid = threadIdx.x;
    const float* arow = V + (size_t)(bm + (tid >> 1)) * 512 + (tid & 1) * 16;
    const uint32_t* bh = Rh + (size_t)t * SZW + bn + (tid & 63);
    const uint32_t* bl = Rl + (size_t)t * SZW + bn + (tid & 63);
    float acc[2][4][4] = {};
    hmma_core_bb(arow, bh, bl, acc);

    const int lane = tid & 31, wid = tid >> 5;
    const int g = lane >> 2, qi = lane & 3;
    const int mo = (wid >> 1) * 32, no = (wid & 1) * 32;
#pragma unroll
    for (int mf = 0; mf < 2; mf++)
#pragma unroll
        for (int f = 0; f < 4; f++) {
            const int col = bn + no + f * 8 + 2 * qi;
#pragma unroll
            for (int h = 0; h < 2; h++) {
                const int r = bm + mo + mf * 16 + g + h * 8;
                const int cidx = r >> 5;       // = c-1
                if (cidx < Cc - 1) {
                    const int b = r & 31;
                    float* op = O + ((size_t)b * Tn + (size_t)(cidx + 1) * Lc + t) * 512 + col;
                    float2 e = *(float2*)op;
                    e.x += acc[mf][f][2 * h];
                    e.y += acc[mf][f][2 * h + 1];
                    *(float2*)op = e;
                }
            }
        }
}

// ---------------------------------------------------------------------------
// pack fp32 matrix [512][512] (k-major) -> word arrays [k/2][512]: hi/lo bf16x2
// ---------------------------------------------------------------------------
__global__ void pack_kernel(const float* __restrict__ src,
                            uint32_t* __restrict__ dh, uint32_t* __restrict__ dl,
                            int total)
{
    const int i = blockIdx.x * 256 + threadIdx.x;
    if (i >= total) return;
    const int z   = i >> 17;        // / SZW
    const int rem = i & (SZW - 1);
    const int w = rem >> 9, n = rem & 511;
    const float* s = src + (size_t)z * SZ + (size_t)(2 * w) * 512 + n;
    const float s0 = s[0], s1 = s[512];
    const uint32_t h = packbf(s0, s1);
    dh[i] = h;
    dl[i] = packbf(s0 - lo_f(h), s1 - hi_f(h));
}

__global__ void copy_floats_kernel(float* __restrict__ dst,
                                   const float* __restrict__ src, int n4)
{
    int i = blockIdx.x * blockDim.x + threadIdx.x;
    if (i < n4) ((float4*)dst)[i] = ((const float4*)src)[i];
}

// V0[c*32+b] = O[b, c*16+15, :].  grid = 2048, block = 128 (float4 per thread)
__global__ void gather_kernel(float* __restrict__ V, const float* __restrict__ O)
{
    const int row = blockIdx.x;
    const int c = row >> 5, b = row & 31;
    const float4* src = (const float4*)(O + ((size_t)b * Tn + (size_t)c * Lc + Lc - 1) * 512);
    ((float4*)(V + (size_t)row * 512))[threadIdx.x] = src[threadIdx.x];
}

// ---------------------------------------------------------------------------
// Launch sequence
// ---------------------------------------------------------------------------
extern "C" void kernel_launch(void* const* d_in, const int* in_sizes, int n_in,
                              void* d_out, int out_size)
{
    const float* x = (const float*)d_in[0];
    const float* w = (const float*)d_in[1];
    const float* r = (const float*)d_in[2];
    float* o = (float*)d_out;
    (void)in_sizes; (void)n_in; (void)out_size;

    float *Rf, *Sf, *V0, *V1;
    uint32_t *Rh, *Rl, *Sh, *Sl, *Wh, *Wl;
    cudaGetSymbolAddress((void**)&Rf, g_Rf);
    cudaGetSymbolAddress((void**)&Rh, g_Rh);
    cudaGetSymbolAddress((void**)&Rl, g_Rl);
    cudaGetSymbolAddress((void**)&Sf, g_Sf);
    cudaGetSymbolAddress((void**)&Sh, g_Sh);
    cudaGetSymbolAddress((void**)&Sl, g_Sl);
    cudaGetSymbolAddress((void**)&Wh, g_Wh);
    cudaGetSymbolAddress((void**)&Wl, g_Wl);
    cudaGetSymbolAddress((void**)&V0, g_V0);
    cudaGetSymbolAddress((void**)&V1, g_V1);

    cudaFuncSetAttribute(hmma_gemm_bb,  cudaFuncAttributeMaxDynamicSharedMemorySize, SMEM_BYTES);
    cudaFuncSetAttribute(hmma_pass1_bb, cudaFuncAttributeMaxDynamicSharedMemorySize, SMEM_BYTES);
    cudaFuncSetAttribute(hmma_scan_step, cudaFuncAttributeMaxDynamicSharedMemorySize, SMEM_BYTES);
    cudaFuncSetAttribute(hmma_pass3_bb, cudaFuncAttributeMaxDynamicSharedMemorySize, SMEM_BYTES);

    // Phase A: pack W, O = X @ W
    pack_kernel<<<SZW / 256, 256>>>(w, Wh, Wl, SZW);
    hmma_gemm_bb<<<dim3(8, M / 128, 1), 256, SMEM_BYTES>>>(x, Wh, Wl, o, 0, 0, 0);

    // Phase B: R power ladder (R^1..R^16) with per-level packing
    copy_floats_kernel<<<SZ / 4 / 256, 256>>>(Rf, r, SZ / 4);
    pack_kernel<<<SZW / 256, 256>>>(r, Rh, Rl, SZW);
    for (int n = 1; n < Lc; n <<= 1) {
        // R^{n+z+1} = R^{z+1} @ R^n, z = 0..n-1
        hmma_gemm_bb<<<dim3(8, 4, n), 256, SMEM_BYTES>>>(
            Rf, Rh + (size_t)(n - 1) * SZW, Rl + (size_t)(n - 1) * SZW,
            Rf + (size_t)n * SZ, SZ, 0, SZ);
        pack_kernel<<<(n * SZW) / 256, 256>>>(
            Rf + (size_t)n * SZ, Rh + (size_t)n * SZW, Rl + (size_t)n * SZW, n * SZW);
    }

    // S ladder: S^{2^i}, i=0..5.  i=0 -> R^16 (already have). i>=1 by squaring.
    for (int i = 1; i <= 5; i++) {
        const float*    Af  = (i == 1) ? (Rf + (size_t)15 * SZ) : (Sf + (size_t)(i - 2) * SZ);
        const uint32_t* Bph = (i == 1) ? (Rh + (size_t)15 * SZW) : (Sh + (size_t)(i - 2) * SZW);
        const uint32_t* Bpl = (i == 1) ? (Rl + (size_t)15 * SZW) : (Sl + (size_t)(i - 2) * SZW);
        hmma_gemm_bb<<<dim3(8, 4, 1), 256, SMEM_BYTES>>>(
            Af, Bph, Bpl, Sf + (size_t)(i - 1) * SZ, 0, 0, 0);
        pack_kernel<<<SZW / 256, 256>>>(
            Sf + (size_t)(i - 1) * SZ, Sh + (size_t)(i - 1) * SZW, Sl + (size_t)(i - 1) * SZW, SZW);
    }

    // Phase C: local scans, 15 sequential steps
    for (int t = 1; t < Lc; t++)
        hmma_pass1_bb<<<dim3(8, 16), 256, SMEM_BYTES>>>(Rh, Rl, o, t);

    // Phase D: carry scan (Hillis-Steele over 64 chunk states)
    gather_kernel<<<Cc * Bn, 128>>>(V0, o);
    const float* vin = V0;
    float* vout = V1;
    for (int i = 0; i < 6; i++) {
        const int d = 1 << i;
        const uint32_t* Sph = (i == 0) ? (Rh + (size_t)15 * SZW) : (Sh + (size_t)(i - 1) * SZW);
        const uint32_t* Spl = (i == 0) ? (Rl + (size_t)15 * SZW) : (Sl + (size_t)(i - 1) * SZW);
        hmma_scan_step<<<dim3(8, 16), 256, SMEM_BYTES>>>(vout, vin, Sph, Spl, d);
        const float* tmp = vin; vin = vout; vout = (float*)tmp;
    }
    // after 6 steps result is back in V0 (vin == V0)

    // Phase E: batched correction
    hmma_pass3_bb<<<dim3(8, 16, 16), 256, SMEM_BYTES>>>(o, vin, Rh, Rl);
}

// round 9
// speedup vs baseline: 9.1606x; 1.0800x over previous
#include <cuda_runtime.h>
#include <cuda_bf16.h>
#include <cstdint>

namespace {
constexpr int Bn = 32;
constexpr int Tn = 1024;
constexpr int M  = Bn * Tn;

constexpr int Lc = 16;
constexpr int Cc = Tn / Lc;         // 64

constexpr int SZ  = 512 * 512;      // fp32 elements per matrix
constexpr int SZW = 256 * 512;      // packed bf16x2 words per matrix
constexpr int WST = 20;             // smem row stride in words
constexpr int BUFW = 7680;          // words per stage buffer
constexpr int SMEM_BYTES = 2 * BUFW * 4;   // 61440
}

// ---------------------------------------------------------------------------
// Static device scratch
// ---------------------------------------------------------------------------
__device__ float    g_Rf[16 * SZ];      // R^1..R^16 fp32
__device__ uint32_t g_Rh[16 * SZW];     // packed bf16 hi of R^1..R^16
__device__ uint32_t g_Rl[16 * SZW];
__device__ float    g_Sf[5 * SZ];       // S^2,S^4,S^8,S^16,S^32 (S = R^16)
__device__ uint32_t g_Sh[5 * SZW];
__device__ uint32_t g_Sl[5 * SZW];
__device__ uint32_t g_Wh[SZW];
__device__ uint32_t g_Wl[SZW];
__device__ float    g_V0[Cc * Bn * 512];
__device__ float    g_V1[Cc * Bn * 512];

// ---------------------------------------------------------------------------
// helpers
// ---------------------------------------------------------------------------
__device__ __forceinline__ uint32_t packbf(float a, float b) {
    uint32_t r;  // low half = a, high half = b
    asm("cvt.rn.bf16x2.f32 %0, %1, %2;" : "=r"(r) : "f"(b), "f"(a));
    return r;
}
__device__ __forceinline__ float lo_f(uint32_t p) { return __uint_as_float(p << 16); }
__device__ __forceinline__ float hi_f(uint32_t p) { return __uint_as_float(p & 0xFFFF0000u); }

__device__ __forceinline__ void mma16816(float* c, const uint32_t* a,
                                         uint32_t b0, uint32_t b1) {
    asm volatile(
        "mma.sync.aligned.m16n8k16.row.col.f32.bf16.bf16.f32 "
        "{%0,%1,%2,%3}, {%4,%5,%6,%7}, {%8,%9}, {%0,%1,%2,%3};"
        : "+f"(c[0]), "+f"(c[1]), "+f"(c[2]), "+f"(c[3])
        : "r"(a[0]), "r"(a[1]), "r"(a[2]), "r"(a[3]), "r"(b0), "r"(b1));
}

// ---------------------------------------------------------------------------
// Double-buffered HMMA core (identical math to round 8).
// ---------------------------------------------------------------------------
__device__ __forceinline__ void hmma_core_bb(const float* __restrict__ arow,
                                             const uint32_t* __restrict__ bh,
                                             const uint32_t* __restrict__ bl,
                                             float acc[2][4][4])
{
    extern __shared__ uint32_t sw[];
    const int tid  = threadIdx.x;
    const int lane = tid & 31, wid = tid >> 5;
    const int g = lane >> 2, qi = lane & 3;
    const int mo = (wid >> 1) * 32, no = (wid & 1) * 32;

    const int sar = tid >> 1;
    const int saw = (tid & 1) * 8;
    const int sbw = (tid >> 6) * 4;

    float af[16];
    uint32_t bhw[4], blw[4];

    auto LOAD = [&](int kc) {
        const float* ap = arow + kc * 32;
        float4 v;
        v = *(const float4*)(ap + 0);  af[0] = v.x;  af[1] = v.y;  af[2] = v.z;  af[3] = v.w;
        v = *(const float4*)(ap + 4);  af[4] = v.x;  af[5] = v.y;  af[6] = v.z;  af[7] = v.w;
        v = *(const float4*)(ap + 8);  af[8] = v.x;  af[9] = v.y;  af[10] = v.z; af[11] = v.w;
        v = *(const float4*)(ap + 12); af[12] = v.x; af[13] = v.y; af[14] = v.z; af[15] = v.w;
        const int off = (kc * 16 + sbw) * 512;
        bhw[0] = bh[off];        bhw[1] = bh[off + 512];
        bhw[2] = bh[off + 1024]; bhw[3] = bh[off + 1536];
        blw[0] = bl[off];        blw[1] = bl[off + 512];
        blw[2] = bl[off + 1024]; blw[3] = bl[off + 1536];
    };

    auto STORE = [&](int bi) {
        uint32_t h[8], l[8];
#pragma unroll
        for (int j = 0; j < 8; j++) {
            h[j] = packbf(af[2 * j], af[2 * j + 1]);
            l[j] = packbf(af[2 * j] - lo_f(h[j]), af[2 * j + 1] - hi_f(h[j]));
        }
        uint32_t* pA = sw + bi * BUFW + sar * WST + saw;
        *(uint4*)pA        = make_uint4(h[0], h[1], h[2], h[3]);
        *(uint4*)(pA + 4)  = make_uint4(h[4], h[5], h[6], h[7]);
        uint32_t* pAl = pA + 2560;
        *(uint4*)pAl       = make_uint4(l[0], l[1], l[2], l[3]);
        *(uint4*)(pAl + 4) = make_uint4(l[4], l[5], l[6], l[7]);
        uint32_t* pB = sw + bi * BUFW + 5120 + (tid & 63) * WST + sbw;
        *(uint4*)pB          = make_uint4(bhw[0], bhw[1], bhw[2], bhw[3]);
        *(uint4*)(pB + 1280) = make_uint4(blw[0], blw[1], blw[2], blw[3]);
    };

    auto COMPUTE = [&](int bi) {
        const uint32_t* bAh = sw + bi * BUFW;
        const uint32_t* bAl = bAh + 2560;
        const uint32_t* bBh = bAh + 5120;
        const uint32_t* bBl = bAh + 6400;
#pragma unroll
        for (int s = 0; s < 2; s++) {
            const int ws = s * 8;
            uint32_t aH[2][4], aL[2][4];
#pragma unroll
            for (int mf = 0; mf < 2; mf++) {
                const int r0 = mo + mf * 16 + g;
                aH[mf][0] = bAh[r0 * WST + ws + qi];
                aH[mf][1] = bAh[(r0 + 8) * WST + ws + qi];
                aH[mf][2] = bAh[r0 * WST + ws + qi + 4];
                aH[mf][3] = bAh[(r0 + 8) * WST + ws + qi + 4];
                aL[mf][0] = bAl[r0 * WST + ws + qi];
                aL[mf][1] = bAl[(r0 + 8) * WST + ws + qi];
                aL[mf][2] = bAl[r0 * WST + ws + qi + 4];
                aL[mf][3] = bAl[(r0 + 8) * WST + ws + qi + 4];
            }
#pragma unroll
            for (int f = 0; f < 4; f++) {
                const int nr = no + f * 8 + g;
                uint32_t bh0 = bBh[nr * WST + ws + qi];
                uint32_t bh1 = bBh[nr * WST + ws + qi + 4];
                uint32_t bl0 = bBl[nr * WST + ws + qi];
                uint32_t bl1 = bBl[nr * WST + ws + qi + 4];
#pragma unroll
                for (int mf = 0; mf < 2; mf++) {
                    mma16816(acc[mf][f], aH[mf], bh0, bh1);
                    mma16816(acc[mf][f], aH[mf], bl0, bl1);
                    mma16816(acc[mf][f], aL[mf], bh0, bh1);
                }
            }
        }
    };

    LOAD(0);
    STORE(0);
    __syncthreads();
    int cur = 0;
    for (int kc = 0; kc < 16; kc++) {
        if (kc < 15) LOAD(kc + 1);
        COMPUTE(cur);
        if (kc < 15) {
            STORE(cur ^ 1);
            __syncthreads();
            cur ^= 1;
        }
    }
}

// ---------------------------------------------------------------------------
// generic C = A @ B (fp32 out).  grid (n/64, m/128, z).  Used for XW.
// ---------------------------------------------------------------------------
__global__ __launch_bounds__(256, 2) void hmma_gemm_bb(
    const float* __restrict__ A, const uint32_t* __restrict__ Bh,
    const uint32_t* __restrict__ Bl, float* __restrict__ C)
{
    const int bn = blockIdx.x * 64;
    const int bm = blockIdx.y * 128;
    const int tid = threadIdx.x;
    const float* arow = A + (size_t)(bm + (tid >> 1)) * 512 + (tid & 1) * 16;
    const uint32_t* bh = Bh + bn + (tid & 63);
    const uint32_t* bl = Bl + bn + (tid & 63);
    float acc[2][4][4] = {};
    hmma_core_bb(arow, bh, bl, acc);

    const int lane = tid & 31, wid = tid >> 5;
    const int g = lane >> 2, qi = lane & 3;
    const int mo = (wid >> 1) * 32, no = (wid & 1) * 32;
#pragma unroll
    for (int mf = 0; mf < 2; mf++)
#pragma unroll
        for (int f = 0; f < 4; f++) {
            const int r0  = bm + mo + mf * 16 + g;
            const int col = bn + no + f * 8 + 2 * qi;
            *(float2*)(C + (size_t)r0 * 512 + col) =
                make_float2(acc[mf][f][0], acc[mf][f][1]);
            *(float2*)(C + (size_t)(r0 + 8) * 512 + col) =
                make_float2(acc[mf][f][2], acc[mf][f][3]);
        }
}

// ---------------------------------------------------------------------------
// Mega pass1 step: y < 16 -> pass1 tile; y >= 16 -> ladder tile (level for
// this step).  Ladder blocks also emit packed bf16 hi/lo via lane shuffles.
// t==15 pass1 blocks additionally write V0 (carry-scan seed).
// ---------------------------------------------------------------------------
__global__ __launch_bounds__(256, 2) void mega_step_kernel(
    const uint32_t* __restrict__ Rh, const uint32_t* __restrict__ Rl,
    float* __restrict__ O, int t, float* __restrict__ V0,
    const float* __restrict__ LA,
    const uint32_t* __restrict__ LBh, const uint32_t* __restrict__ LBl,
    float* __restrict__ LCf, uint32_t* __restrict__ LCh, uint32_t* __restrict__ LCl)
{
    const int bn  = blockIdx.x * 64;
    const int tid = threadIdx.x;
    const int lane = tid & 31, wid = tid >> 5;
    const int g = lane >> 2, qi = lane & 3;
    const int mo = (wid >> 1) * 32, no = (wid & 1) * 32;

    if (blockIdx.y < 16) {
        // ---- pass1 role: O[b, c*16+t, :] += O[b, c*16+t-1, :] @ R ----
        const int bm = blockIdx.y * 128;
        const int srow = bm + (tid >> 1);
        const float* arow = O + ((size_t)(srow & 31) * Tn + (size_t)(srow >> 5) * Lc + (t - 1)) * 512
                            + (tid & 1) * 16;
        const uint32_t* bh = Rh + bn + (tid & 63);
        const uint32_t* bl = Rl + bn + (tid & 63);
        float acc[2][4][4] = {};
        hmma_core_bb(arow, bh, bl, acc);

#pragma unroll
        for (int mf = 0; mf < 2; mf++)
#pragma unroll
            for (int f = 0; f < 4; f++) {
                const int col = bn + no + f * 8 + 2 * qi;
#pragma unroll
                for (int h = 0; h < 2; h++) {
                    const int r = bm + mo + mf * 16 + g + h * 8;
                    float* op = O + ((size_t)(r & 31) * Tn + (size_t)(r >> 5) * Lc + t) * 512 + col;
                    float2 e = *(float2*)op;
                    e.x += acc[mf][f][2 * h];
                    e.y += acc[mf][f][2 * h + 1];
                    *(float2*)op = e;
                    if (t == Lc - 1)
                        *(float2*)(V0 + (size_t)r * 512 + col) = e;
                }
            }
    } else {
        // ---- ladder role: LC[z] = LA[z] @ LB, plus packed epilogue ----
        const int y2 = blockIdx.y - 16;
        const int z  = y2 >> 2;
        const int mrow = (y2 & 3) * 128;
        const float* arow = LA + (size_t)z * SZ + (size_t)(mrow + (tid >> 1)) * 512 + (tid & 1) * 16;
        const uint32_t* bh = LBh + bn + (tid & 63);
        const uint32_t* bl = LBl + bn + (tid & 63);
        float acc[2][4][4] = {};
        hmma_core_bb(arow, bh, bl, acc);

        float* Cz = LCf + (size_t)z * SZ;
        uint32_t* Dh = LCh + (size_t)z * SZW;
        uint32_t* Dl = LCl + (size_t)z * SZW;
#pragma unroll
        for (int mf = 0; mf < 2; mf++)
#pragma unroll
            for (int f = 0; f < 4; f++) {
                const int r0  = mrow + mo + mf * 16 + g;
                const int col = bn + no + f * 8 + 2 * qi;
                *(float2*)(Cz + (size_t)r0 * 512 + col) =
                    make_float2(acc[mf][f][0], acc[mf][f][1]);
                *(float2*)(Cz + (size_t)(r0 + 8) * 512 + col) =
                    make_float2(acc[mf][f][2], acc[mf][f][3]);

                // packed epilogue: rows (r0, r0+1) pair -> word r0>>1
                float pc0 = __shfl_sync(0xffffffffu, acc[mf][f][0], (lane + 4) & 31);
                float pc1 = __shfl_sync(0xffffffffu, acc[mf][f][1], (lane + 4) & 31);
                float pc2 = __shfl_sync(0xffffffffu, acc[mf][f][2], (lane + 4) & 31);
                float pc3 = __shfl_sync(0xffffffffu, acc[mf][f][3], (lane + 4) & 31);
                if ((g & 1) == 0) {
                    const int w0 = r0 >> 1;          // rows r0, r0+1
                    const int w1 = (r0 + 8) >> 1;    // rows r0+8, r0+9
                    uint32_t h0 = packbf(acc[mf][f][0], pc0);
                    Dh[(size_t)w0 * 512 + col] = h0;
                    Dl[(size_t)w0 * 512 + col] =
                        packbf(acc[mf][f][0] - lo_f(h0), pc0 - hi_f(h0));
                    uint32_t h1 = packbf(acc[mf][f][1], pc1);
                    Dh[(size_t)w0 * 512 + col + 1] = h1;
                    Dl[(size_t)w0 * 512 + col + 1] =
                        packbf(acc[mf][f][1] - lo_f(h1), pc1 - hi_f(h1));
                    uint32_t h2 = packbf(acc[mf][f][2], pc2);
                    Dh[(size_t)w1 * 512 + col] = h2;
                    Dl[(size_t)w1 * 512 + col] =
                        packbf(acc[mf][f][2] - lo_f(h2), pc2 - hi_f(h2));
                    uint32_t h3 = packbf(acc[mf][f][3], pc3);
                    Dh[(size_t)w1 * 512 + col + 1] = h3;
                    Dl[(size_t)w1 * 512 + col + 1] =
                        packbf(acc[mf][f][3] - lo_f(h3), pc3 - hi_f(h3));
                }
            }
    }
}

// ---------------------------------------------------------------------------
// Hillis-Steele scan step: Vout[c] = Vin[c] + (c>=d ? Vin[c-d] @ S^d : 0)
// ---------------------------------------------------------------------------
__global__ __launch_bounds__(256, 2) void hmma_scan_step(
    float* __restrict__ Vout, const float* __restrict__ Vin,
    const uint32_t* __restrict__ Sh, const uint32_t* __restrict__ Sl, int d)
{
    const int bn = blockIdx.x * 64;
    const int bm = blockIdx.y * 128;
    const int tid = threadIdx.x;
    const int srow = bm + (tid >> 1);
    const int csrc = (srow >> 5) - d;
    const int asrc = (csrc >= 0) ? (csrc * 32 + (srow & 31)) : srow;
    const float* arow = Vin + (size_t)asrc * 512 + (tid & 1) * 16;
    const uint32_t* bh = Sh + bn + (tid & 63);
    const uint32_t* bl = Sl + bn + (tid & 63);
    float acc[2][4][4] = {};
    hmma_core_bb(arow, bh, bl, acc);

    const int lane = tid & 31, wid = tid >> 5;
    const int g = lane >> 2, qi = lane & 3;
    const int mo = (wid >> 1) * 32, no = (wid & 1) * 32;
#pragma unroll
    for (int mf = 0; mf < 2; mf++)
#pragma unroll
        for (int f = 0; f < 4; f++) {
            const int col = bn + no + f * 8 + 2 * qi;
#pragma unroll
            for (int h = 0; h < 2; h++) {
                const int r = bm + mo + mf * 16 + g + h * 8;
                float2 e = *(const float2*)(Vin + (size_t)r * 512 + col);
                if ((r >> 5) >= d) {
                    e.x += acc[mf][f][2 * h];
                    e.y += acc[mf][f][2 * h + 1];
                }
                *(float2*)(Vout + (size_t)r * 512 + col) = e;
            }
        }
}

// ---------------------------------------------------------------------------
// pass3: O[b, 16*(c+1)+t, :] += V[c] @ R^{t+1}.  grid (8, 16, 16: t)
// ---------------------------------------------------------------------------
__global__ __launch_bounds__(256, 2) void hmma_pass3_bb(
    float* __restrict__ O, const float* __restrict__ V,
    const uint32_t* __restrict__ Rh, const uint32_t* __restrict__ Rl)
{
    const int t  = blockIdx.z;
    const int bn = blockIdx.x * 64;
    const int bm = blockIdx.y * 128;
    const int tid = threadIdx.x;
    const float* arow = V + (size_t)(bm + (tid >> 1)) * 512 + (tid & 1) * 16;
    const uint32_t* bh = Rh + (size_t)t * SZW + bn + (tid & 63);
    const uint32_t* bl = Rl + (size_t)t * SZW + bn + (tid & 63);
    float acc[2][4][4] = {};
    hmma_core_bb(arow, bh, bl, acc);

    const int lane = tid & 31, wid = tid >> 5;
    const int g = lane >> 2, qi = lane & 3;
    const int mo = (wid >> 1) * 32, no = (wid & 1) * 32;
#pragma unroll
    for (int mf = 0; mf < 2; mf++)
#pragma unroll
        for (int f = 0; f < 4; f++) {
            const int col = bn + no + f * 8 + 2 * qi;
#pragma unroll
            for (int h = 0; h < 2; h++) {
                const int r = bm + mo + mf * 16 + g + h * 8;
                const int cidx = r >> 5;       // = c-1
                if (cidx < Cc - 1) {
                    const int b = r & 31;
                    float* op = O + ((size_t)b * Tn + (size_t)(cidx + 1) * Lc + t) * 512 + col;
                    float2 e = *(float2*)op;
                    e.x += acc[mf][f][2 * h];
                    e.y += acc[mf][f][2 * h + 1];
                    *(float2*)op = e;
                }
            }
        }
}

// ---------------------------------------------------------------------------
// utilities
// ---------------------------------------------------------------------------
__global__ void pack_kernel(const float* __restrict__ src,
                            uint32_t* __restrict__ dh, uint32_t* __restrict__ dl,
                            int total)
{
    const int i = blockIdx.x * 256 + threadIdx.x;
    if (i >= total) return;
    const int w = i >> 9, n = i & 511;
    const float* s = src + (size_t)(2 * w) * 512 + n;
    const float s0 = s[0], s1 = s[512];
    const uint32_t h = packbf(s0, s1);
    dh[i] = h;
    dl[i] = packbf(s0 - lo_f(h), s1 - hi_f(h));
}

__global__ void copy_floats_kernel(float* __restrict__ dst,
                                   const float* __restrict__ src, int n4)
{
    int i = blockIdx.x * blockDim.x + threadIdx.x;
    if (i < n4) ((float4*)dst)[i] = ((const float4*)src)[i];
}

// ---------------------------------------------------------------------------
// Launch sequence
// ---------------------------------------------------------------------------
extern "C" void kernel_launch(void* const* d_in, const int* in_sizes, int n_in,
                              void* d_out, int out_size)
{
    const float* x = (const float*)d_in[0];
    const float* w = (const float*)d_in[1];
    const float* r = (const float*)d_in[2];
    float* o = (float*)d_out;
    (void)in_sizes; (void)n_in; (void)out_size;

    float *Rf, *Sf, *V0, *V1;
    uint32_t *Rh, *Rl, *Sh, *Sl, *Wh, *Wl;
    cudaGetSymbolAddress((void**)&Rf, g_Rf);
    cudaGetSymbolAddress((void**)&Rh, g_Rh);
    cudaGetSymbolAddress((void**)&Rl, g_Rl);
    cudaGetSymbolAddress((void**)&Sf, g_Sf);
    cudaGetSymbolAddress((void**)&Sh, g_Sh);
    cudaGetSymbolAddress((void**)&Sl, g_Sl);
    cudaGetSymbolAddress((void**)&Wh, g_Wh);
    cudaGetSymbolAddress((void**)&Wl, g_Wl);
    cudaGetSymbolAddress((void**)&V0, g_V0);
    cudaGetSymbolAddress((void**)&V1, g_V1);

    cudaFuncSetAttribute(hmma_gemm_bb,   cudaFuncAttributeMaxDynamicSharedMemorySize, SMEM_BYTES);
    cudaFuncSetAttribute(mega_step_kernel, cudaFuncAttributeMaxDynamicSharedMemorySize, SMEM_BYTES);
    cudaFuncSetAttribute(hmma_scan_step, cudaFuncAttributeMaxDynamicSharedMemorySize, SMEM_BYTES);
    cudaFuncSetAttribute(hmma_pass3_bb,  cudaFuncAttributeMaxDynamicSharedMemorySize, SMEM_BYTES);

    // Prologue: pack W and R, seed Rf slot 0 with R^1.
    pack_kernel<<<SZW / 256, 256>>>(w, Wh, Wl, SZW);
    pack_kernel<<<SZW / 256, 256>>>(r, Rh, Rl, SZW);
    copy_floats_kernel<<<SZ / 4 / 256, 256>>>(Rf, r, SZ / 4);

    // Phase A: O = X @ W
    hmma_gemm_bb<<<dim3(8, M / 128), 256, SMEM_BYTES>>>(x, Wh, Wl, o);

    // Phase C + B: pass1 steps with ladder piggyback.
    // Ladder schedule per step t: {LA, LBh, LBl, LCf, LCh, LCl, lmt}
    struct Lad { const float* A; const uint32_t *Bh, *Bl; float* Cf; uint32_t *Ch, *Cl; int mt; };
    Lad lad[16];
    for (int t = 0; t < 16; t++) lad[t] = {o, Rh, Rl, Rf, Rh, Rl, 0};  // defaults unused
    lad[1]  = {r,            Rh,            Rl,            Rf + (size_t)1 * SZ,  Rh + (size_t)1 * SZW,  Rl + (size_t)1 * SZW,  4};   // R^2
    lad[2]  = {Rf,           Rh + 1 * SZW,  Rl + 1 * SZW,  Rf + (size_t)2 * SZ,  Rh + (size_t)2 * SZW,  Rl + (size_t)2 * SZW,  8};   // R^3,R^4
    lad[3]  = {Rf,           Rh + 3 * SZW,  Rl + 3 * SZW,  Rf + (size_t)4 * SZ,  Rh + (size_t)4 * SZW,  Rl + (size_t)4 * SZW,  16};  // R^5..R^8
    lad[4]  = {Rf,           Rh + 7 * SZW,  Rl + 7 * SZW,  Rf + (size_t)8 * SZ,  Rh + (size_t)8 * SZW,  Rl + (size_t)8 * SZW,  32};  // R^9..R^16
    lad[5]  = {Rf + 15 * SZ, Rh + 15 * SZW, Rl + 15 * SZW, Sf,                   Sh,                    Sl,                    4};   // S^2
    lad[6]  = {Sf,           Sh,            Sl,            Sf + (size_t)1 * SZ,  Sh + (size_t)1 * SZW,  Sl + (size_t)1 * SZW,  4};   // S^4
    lad[7]  = {Sf + 1 * SZ,  Sh + 1 * SZW,  Sl + 1 * SZW,  Sf + (size_t)2 * SZ,  Sh + (size_t)2 * SZW,  Sl + (size_t)2 * SZW,  4};   // S^8
    lad[8]  = {Sf + 2 * SZ,  Sh + 2 * SZW,  Sl + 2 * SZW,  Sf + (size_t)3 * SZ,  Sh + (size_t)3 * SZW,  Sl + (size_t)3 * SZW,  4};   // S^16
    lad[9]  = {Sf + 3 * SZ,  Sh + 3 * SZW,  Sl + 3 * SZW,  Sf + (size_t)4 * SZ,  Sh + (size_t)4 * SZW,  Sl + (size_t)4 * SZW,  4};   // S^32

    for (int t = 1; t < Lc; t++) {
        const Lad& L = lad[t];
        mega_step_kernel<<<dim3(8, 16 + L.mt), 256, SMEM_BYTES>>>(
            Rh, Rl, o, t, V0, L.A, L.Bh, L.Bl, L.Cf, L.Ch, L.Cl);
    }

    // Phase D: carry scan (Hillis-Steele over 64 chunk states)
    const float* vin = V0;
    float* vout = V1;
    for (int i = 0; i < 6; i++) {
        const int d = 1 << i;
        const uint32_t* Sph = (i == 0) ? (Rh + (size_t)15 * SZW) : (Sh + (size_t)(i - 1) * SZW);
        const uint32_t* Spl = (i == 0) ? (Rl + (size_t)15 * SZW) : (Sl + (size_t)(i - 1) * SZW);
        hmma_scan_step<<<dim3(8, 16), 256, SMEM_BYTES>>>(vout, vin, Sph, Spl, d);
        const float* tmp = vin; vin = vout; vout = (float*)tmp;
    }

    // Phase E: batched correction
    hmma_pass3_bb<<<dim3(8, 16, 16), 256, SMEM_BYTES>>>(o, vin, Rh, Rl);
}